// round 6
// baseline (speedup 1.0000x reference)
#include <cuda_runtime.h>
#include <cuda_bf16.h>
#include <cstdint>

// ---------------- problem constants ----------------
#define E_DIM 128
#define L_DIM 256
#define H_DIM 12
#define DH_DIM 64
#define D_DIM 768          // H*DH
#define TD_DIM 2304        // 3*D
#define N_ROWS 32768       // E*L
#define LN_EPS 1e-5f

// ---------------- scratch (__device__ globals; no cudaMalloc allowed) ----------------
__device__ float g_proj[(size_t)N_ROWS * TD_DIM];          // QKV projection     (~302 MB)
__device__ float g_scores[(size_t)H_DIM * L_DIM * L_DIM];  // row scores/maps    (~3 MB)
__device__ float g_lnstats[N_ROWS * 2];                    // per-row mu, rstd   (256 KB)
__device__ float g_rowmask[H_DIM * L_DIM];                 // sum_e mask[h,e,j]

// ---------------- tf32 helpers ----------------
__device__ __forceinline__ unsigned f2tf32(float x) {
    unsigned u;
    asm("cvt.rna.tf32.f32 %0, %1;" : "=r"(u) : "f"(x));
    return u;
}
__device__ __forceinline__ void mma_tf32(float* d, const unsigned* a, const unsigned* b) {
    asm volatile(
        "mma.sync.aligned.m16n8k8.row.col.f32.tf32.tf32.f32 "
        "{%0,%1,%2,%3}, {%4,%5,%6,%7}, {%8,%9}, {%0,%1,%2,%3};\n"
        : "+f"(d[0]), "+f"(d[1]), "+f"(d[2]), "+f"(d[3])
        : "r"(a[0]), "r"(a[1]), "r"(a[2]), "r"(a[3]), "r"(b[0]), "r"(b[1]));
}

// ---------------- reductions ----------------
__device__ __forceinline__ float warp_sum(float v) {
#pragma unroll
    for (int o = 16; o; o >>= 1) v += __shfl_xor_sync(0xffffffffu, v, o);
    return v;
}
__device__ __forceinline__ float warp_max(float v) {
#pragma unroll
    for (int o = 16; o; o >>= 1) v = fmaxf(v, __shfl_xor_sync(0xffffffffu, v, o));
    return v;
}
__device__ __forceinline__ float block_sum256(float v, float* red) {
    int lane = threadIdx.x & 31, w = threadIdx.x >> 5;
    v = warp_sum(v);
    if (lane == 0) red[w] = v;
    __syncthreads();
    if (threadIdx.x < 8) {
        float r = red[threadIdx.x];
        r += __shfl_xor_sync(0xffu, r, 4);
        r += __shfl_xor_sync(0xffu, r, 2);
        r += __shfl_xor_sync(0xffu, r, 1);
        if (threadIdx.x == 0) red[0] = r;
    }
    __syncthreads();
    float out = red[0];
    __syncthreads();
    return out;
}
__device__ __forceinline__ float block_max256(float v, float* red) {
    int lane = threadIdx.x & 31, w = threadIdx.x >> 5;
    v = warp_max(v);
    if (lane == 0) red[w] = v;
    __syncthreads();
    if (threadIdx.x < 8) {
        float r = red[threadIdx.x];
        r = fmaxf(r, __shfl_xor_sync(0xffu, r, 4));
        r = fmaxf(r, __shfl_xor_sync(0xffu, r, 2));
        r = fmaxf(r, __shfl_xor_sync(0xffu, r, 1));
        if (threadIdx.x == 0) red[0] = r;
    }
    __syncthreads();
    float out = red[0];
    __syncthreads();
    return out;
}

// ---------------- K1/K6: LayerNorm stats only (mu, rstd per row) ----------------
__global__ __launch_bounds__(256) void ln_stats_kernel(const float* __restrict__ x) {
    __shared__ float red[8];
    const size_t base = (size_t)blockIdx.x * D_DIM;
    const int t = threadIdx.x;
    float v0 = x[base + t];
    float v1 = x[base + t + 256];
    float v2 = x[base + t + 512];
    float s1 = block_sum256(v0 + v1 + v2, red);
    float s2 = block_sum256(v0 * v0 + v1 * v1 + v2 * v2, red);
    const float inv_d = 1.0f / (float)D_DIM;
    float mu = s1 * inv_d;
    float var = fmaxf(s2 * inv_d - mu * mu, 0.0f);
    if (t == 0) {
        g_lnstats[blockIdx.x * 2 + 0] = mu;
        g_lnstats[blockIdx.x * 2 + 1] = rsqrtf(var + LN_EPS);
    }
}

// ---------------- K2/K7: fused LN + QKV GEMM (tensor cores, 3xTF32, pre-split smem) ----
// C[N,2304] = LN(x)[N,768] * W[2304,768]^T + bias
// Block tile 128x128, warp tile 32x64 (8 warps). hi/lo tf32 split done at stage time.
__global__ __launch_bounds__(256, 2) void qkv_gemm_tc(const float* __restrict__ x,
                                                      const float* __restrict__ W,
                                                      const float* __restrict__ bias,
                                                      const float* __restrict__ gamma,
                                                      const float* __restrict__ beta) {
    __shared__ unsigned As_h[16][136], As_l[16][136];
    __shared__ unsigned Bs_h[16][136], Bs_l[16][136];
    __shared__ float mu_s[128], rs_s[128];
    const int tid = threadIdx.x;
    const int wid = tid >> 5, lane = tid & 31;
    const int warp_m = (wid >> 1) * 32;      // 0,32,64,96
    const int warp_n = (wid & 1) * 64;       // 0,64
    const int r = lane >> 2, c = lane & 3;
    const int m0 = blockIdx.y * 128;
    const int n0 = blockIdx.x * 128;

    if (tid < 128) {
        mu_s[tid] = g_lnstats[(m0 + tid) * 2 + 0];
        rs_s[tid] = g_lnstats[(m0 + tid) * 2 + 1];
    }

    float acc[2][8][4];
#pragma unroll
    for (int t = 0; t < 2; t++)
#pragma unroll
        for (int u = 0; u < 8; u++)
#pragma unroll
            for (int v = 0; v < 4; v++) acc[t][u][v] = 0.0f;
    __syncthreads();

    for (int k0 = 0; k0 < D_DIM; k0 += 16) {
        // ---- stage tiles: LN + tf32 hi/lo split once per element ----
#pragma unroll
        for (int q = 0; q < 2; q++) {
            int id = q * 256 + tid;          // 512 float4 per tile
            int rr = id >> 2;                // m or n row
            int c4 = (id & 3) << 2;          // k offset
            float4 va = *(const float4*)(x + (size_t)(m0 + rr) * D_DIM + k0 + c4);
            float4 gm = *(const float4*)(gamma + k0 + c4);
            float4 bt = *(const float4*)(beta + k0 + c4);
            float mu = mu_s[rr], rs = rs_s[rr];
            float f0 = (va.x - mu) * rs * gm.x + bt.x;
            float f1 = (va.y - mu) * rs * gm.y + bt.y;
            float f2 = (va.z - mu) * rs * gm.z + bt.z;
            float f3 = (va.w - mu) * rs * gm.w + bt.w;
            unsigned h;
            h = f2tf32(f0); As_h[c4 + 0][rr] = h; As_l[c4 + 0][rr] = f2tf32(f0 - __uint_as_float(h));
            h = f2tf32(f1); As_h[c4 + 1][rr] = h; As_l[c4 + 1][rr] = f2tf32(f1 - __uint_as_float(h));
            h = f2tf32(f2); As_h[c4 + 2][rr] = h; As_l[c4 + 2][rr] = f2tf32(f2 - __uint_as_float(h));
            h = f2tf32(f3); As_h[c4 + 3][rr] = h; As_l[c4 + 3][rr] = f2tf32(f3 - __uint_as_float(h));
            float4 vb = *(const float4*)(W + (size_t)(n0 + rr) * D_DIM + k0 + c4);
            h = f2tf32(vb.x); Bs_h[c4 + 0][rr] = h; Bs_l[c4 + 0][rr] = f2tf32(vb.x - __uint_as_float(h));
            h = f2tf32(vb.y); Bs_h[c4 + 1][rr] = h; Bs_l[c4 + 1][rr] = f2tf32(vb.y - __uint_as_float(h));
            h = f2tf32(vb.z); Bs_h[c4 + 2][rr] = h; Bs_l[c4 + 2][rr] = f2tf32(vb.z - __uint_as_float(h));
            h = f2tf32(vb.w); Bs_h[c4 + 3][rr] = h; Bs_l[c4 + 3][rr] = f2tf32(vb.w - __uint_as_float(h));
        }
        __syncthreads();

        // ---- compute: pure LDS + MMA ----
#pragma unroll
        for (int k8 = 0; k8 < 16; k8 += 8) {
            unsigned Ah[2][4], Al[2][4];
#pragma unroll
            for (int t = 0; t < 2; t++) {
                int m = warp_m + t * 16 + r;
                Ah[t][0] = As_h[k8 + c][m];     Al[t][0] = As_l[k8 + c][m];
                Ah[t][1] = As_h[k8 + c][m + 8]; Al[t][1] = As_l[k8 + c][m + 8];
                Ah[t][2] = As_h[k8 + c + 4][m];     Al[t][2] = As_l[k8 + c + 4][m];
                Ah[t][3] = As_h[k8 + c + 4][m + 8]; Al[t][3] = As_l[k8 + c + 4][m + 8];
            }
#pragma unroll
            for (int u = 0; u < 8; u++) {
                int n = warp_n + u * 8 + r;
                unsigned Bh[2], Bl[2];
                Bh[0] = Bs_h[k8 + c][n];     Bl[0] = Bs_l[k8 + c][n];
                Bh[1] = Bs_h[k8 + 4 + c][n]; Bl[1] = Bs_l[k8 + 4 + c][n];
#pragma unroll
                for (int t = 0; t < 2; t++) {
                    mma_tf32(acc[t][u], Ah[t], Bh);
                    mma_tf32(acc[t][u], Ah[t], Bl);
                    mma_tf32(acc[t][u], Al[t], Bh);
                }
            }
        }
        __syncthreads();
    }

    // ---- epilogue: bias add + store ----
#pragma unroll
    for (int t = 0; t < 2; t++) {
        int row0 = m0 + warp_m + t * 16 + r;
#pragma unroll
        for (int u = 0; u < 8; u++) {
            int col = n0 + warp_n + u * 8 + c * 2;
            float2 bz = *(const float2*)(bias + col);
            float2 v0, v1;
            v0.x = acc[t][u][0] + bz.x; v0.y = acc[t][u][1] + bz.y;
            v1.x = acc[t][u][2] + bz.x; v1.y = acc[t][u][3] + bz.y;
            *(float2*)(g_proj + (size_t)row0 * TD_DIM + col) = v0;
            *(float2*)(g_proj + (size_t)(row0 + 8) * TD_DIM + col) = v1;
        }
    }
}

// ---------------- K3a: zero scores + row mask sums ----------------
__global__ __launch_bounds__(256) void scores_zero_kernel(const float* __restrict__ mask) {
    size_t idx = (size_t)blockIdx.x * 1024 + threadIdx.x * 4;
    if (idx < (size_t)H_DIM * L_DIM * L_DIM) {
        float4 z = {0.f, 0.f, 0.f, 0.f};
        *(float4*)(g_scores + idx) = z;
    }
    int t = blockIdx.x * 256 + threadIdx.x;   // [0, H*L)
    if (t < H_DIM * L_DIM) {
        int h = t / L_DIM, j = t % L_DIM;
        float s = 0.0f;
        for (int e = 0; e < E_DIM; e++) s += mask[((size_t)h * E_DIM + e) * L_DIM + j];
        g_rowmask[t] = s;
    }
}

// ---------------- K3b: row scores (tensor cores, 3xTF32) -------------------------
// scores[h,i,j] += sum_{e,c} q[e,i,h,c] k[e,j,h,c]
// grid: (4 [2x2 ij-tiles], H, 4 [e-split]); block tile 128x128, K=32e*64c=2048.
__global__ __launch_bounds__(256, 2) void row_scores_tc() {
    __shared__ unsigned As_h[16][136], As_l[16][136];
    __shared__ unsigned Bs_h[16][136], Bs_l[16][136];
    const int tid = threadIdx.x;
    const int wid = tid >> 5, lane = tid & 31;
    const int warp_m = (wid >> 1) * 32;
    const int warp_n = (wid & 1) * 64;
    const int r = lane >> 2, c = lane & 3;
    const int it = (blockIdx.x >> 1) * 128;
    const int jt = (blockIdx.x & 1) * 128;
    const int h = blockIdx.y;
    const int e0 = blockIdx.z * 32;

    float acc[2][8][4];
#pragma unroll
    for (int t = 0; t < 2; t++)
#pragma unroll
        for (int u = 0; u < 8; u++)
#pragma unroll
            for (int v = 0; v < 4; v++) acc[t][u][v] = 0.0f;

    for (int e = e0; e < e0 + 32; e++) {
        const float* qbase = g_proj + (size_t)(e * L_DIM) * TD_DIM + h * DH_DIM;
        const float* kbase = qbase + D_DIM;
        for (int k0 = 0; k0 < DH_DIM; k0 += 16) {
#pragma unroll
            for (int q = 0; q < 2; q++) {
                int id = q * 256 + tid;
                int rr = id >> 2;
                int c4 = (id & 3) << 2;
                float4 va = *(const float4*)(qbase + (size_t)(it + rr) * TD_DIM + k0 + c4);
                unsigned hh;
                hh = f2tf32(va.x); As_h[c4 + 0][rr] = hh; As_l[c4 + 0][rr] = f2tf32(va.x - __uint_as_float(hh));
                hh = f2tf32(va.y); As_h[c4 + 1][rr] = hh; As_l[c4 + 1][rr] = f2tf32(va.y - __uint_as_float(hh));
                hh = f2tf32(va.z); As_h[c4 + 2][rr] = hh; As_l[c4 + 2][rr] = f2tf32(va.z - __uint_as_float(hh));
                hh = f2tf32(va.w); As_h[c4 + 3][rr] = hh; As_l[c4 + 3][rr] = f2tf32(va.w - __uint_as_float(hh));
                float4 vb = *(const float4*)(kbase + (size_t)(jt + rr) * TD_DIM + k0 + c4);
                hh = f2tf32(vb.x); Bs_h[c4 + 0][rr] = hh; Bs_l[c4 + 0][rr] = f2tf32(vb.x - __uint_as_float(hh));
                hh = f2tf32(vb.y); Bs_h[c4 + 1][rr] = hh; Bs_l[c4 + 1][rr] = f2tf32(vb.y - __uint_as_float(hh));
                hh = f2tf32(vb.z); Bs_h[c4 + 2][rr] = hh; Bs_l[c4 + 2][rr] = f2tf32(vb.z - __uint_as_float(hh));
                hh = f2tf32(vb.w); Bs_h[c4 + 3][rr] = hh; Bs_l[c4 + 3][rr] = f2tf32(vb.w - __uint_as_float(hh));
            }
            __syncthreads();
#pragma unroll
            for (int k8 = 0; k8 < 16; k8 += 8) {
                unsigned Ah[2][4], Al[2][4];
#pragma unroll
                for (int t = 0; t < 2; t++) {
                    int m = warp_m + t * 16 + r;
                    Ah[t][0] = As_h[k8 + c][m];     Al[t][0] = As_l[k8 + c][m];
                    Ah[t][1] = As_h[k8 + c][m + 8]; Al[t][1] = As_l[k8 + c][m + 8];
                    Ah[t][2] = As_h[k8 + c + 4][m];     Al[t][2] = As_l[k8 + c + 4][m];
                    Ah[t][3] = As_h[k8 + c + 4][m + 8]; Al[t][3] = As_l[k8 + c + 4][m + 8];
                }
#pragma unroll
                for (int u = 0; u < 8; u++) {
                    int n = warp_n + u * 8 + r;
                    unsigned Bh[2], Bl[2];
                    Bh[0] = Bs_h[k8 + c][n];     Bl[0] = Bs_l[k8 + c][n];
                    Bh[1] = Bs_h[k8 + 4 + c][n]; Bl[1] = Bs_l[k8 + 4 + c][n];
#pragma unroll
                    for (int t = 0; t < 2; t++) {
                        mma_tf32(acc[t][u], Ah[t], Bh);
                        mma_tf32(acc[t][u], Ah[t], Bl);
                        mma_tf32(acc[t][u], Al[t], Bh);
                    }
                }
            }
            __syncthreads();
        }
    }

    // ---- epilogue: atomic accumulate (split-e) ----
#pragma unroll
    for (int t = 0; t < 2; t++) {
        int row = it + warp_m + t * 16 + r;
#pragma unroll
        for (int u = 0; u < 8; u++) {
            int col = jt + warp_n + u * 8 + c * 2;
            float* p0 = &g_scores[((size_t)h * L_DIM + row) * L_DIM + col];
            atomicAdd(p0, acc[t][u][0]);
            atomicAdd(p0 + 1, acc[t][u][1]);
            float* p1 = &g_scores[((size_t)h * L_DIM + row + 8) * L_DIM + col];
            atomicAdd(p1, acc[t][u][2]);
            atomicAdd(p1 + 1, acc[t][u][3]);
        }
    }
}

// ---------------- K4: softmax over j (adds row mask on the fly) ----------------
__global__ __launch_bounds__(256) void row_softmax_kernel() {
    __shared__ float red[8];
    int h = blockIdx.x / L_DIM;
    float* row = g_scores + (size_t)blockIdx.x * L_DIM;
    float v = row[threadIdx.x] + g_rowmask[h * L_DIM + threadIdx.x];
    float m = block_max256(v, red);
    float p = __expf(v - m);
    float s = block_sum256(p, red);
    row[threadIdx.x] = p / s;
}

// ---------------- K5: row AV + residual ----------------
__global__ __launch_bounds__(256) void row_av_kernel(const float* __restrict__ x,
                                                     float* __restrict__ out) {
    __shared__ float Ms[64][64];  // [jj][i]
    __shared__ float Vs[64][64];  // [jj][c]
    const int tid = threadIdx.x;
    const int tx = tid & 15, ty = tid >> 4;
    const int it = blockIdx.x * 64;
    const int h = blockIdx.y;
    const int e = blockIdx.z;
    const float* vbase = g_proj + (size_t)(e * L_DIM) * TD_DIM + 2 * D_DIM + h * DH_DIM;
    float acc[4][4];
#pragma unroll
    for (int i = 0; i < 4; i++)
#pragma unroll
        for (int j = 0; j < 4; j++) acc[i][j] = 0.0f;

    for (int j0 = 0; j0 < L_DIM; j0 += 64) {
#pragma unroll
        for (int q = 0; q < 4; q++) {
            int id = q * 256 + tid;
            int rI = id & 63;
            int c4 = ((id >> 6) & 15) << 2;
            float4 vm = *(const float4*)(g_scores + ((size_t)h * L_DIM + it + rI) * L_DIM + j0 + c4);
            Ms[c4 + 0][rI] = vm.x; Ms[c4 + 1][rI] = vm.y; Ms[c4 + 2][rI] = vm.z; Ms[c4 + 3][rI] = vm.w;
            int rJ = id >> 4;
            int c42 = (id & 15) << 2;
            *(float4*)&Vs[rJ][c42] = *(const float4*)(vbase + (size_t)(j0 + rJ) * TD_DIM + c42);
        }
        __syncthreads();
#pragma unroll
        for (int jj = 0; jj < 64; jj++) {
            float a[4], b[4];
            *(float4*)a = *(const float4*)&Ms[jj][ty * 4];
            *(float4*)b = *(const float4*)&Vs[jj][tx * 4];
#pragma unroll
            for (int i = 0; i < 4; i++)
#pragma unroll
                for (int j = 0; j < 4; j++) acc[i][j] = fmaf(a[i], b[j], acc[i][j]);
        }
        __syncthreads();
    }
#pragma unroll
    for (int i = 0; i < 4; i++) {
        int li = it + ty * 4 + i;
        size_t off = ((size_t)(e * L_DIM + li)) * D_DIM + h * DH_DIM + tx * 4;
        float4 xr = *(const float4*)(x + off);
        float4 v;
        v.x = xr.x + acc[i][0];
        v.y = xr.y + acc[i][1];
        v.z = xr.z + acc[i][2];
        v.w = xr.w + acc[i][3];
        *(float4*)(out + off) = v;
    }
}

// ---------------- K8: fused column attention, one block per (h,l) ----------------
// Q tile staged into the Ss buffer (overwritten by S after compute) -> no gmem
// streaming in the S inner loop, no extra smem.
#define COL_SMEM_FLOATS (64 * 128 + 128 * 64 + 128 * 128 + 256)
__global__ __launch_bounds__(256) void col_attn_kernel(const float* __restrict__ mask,
                                                       float* __restrict__ out) {
    extern __shared__ float sm[];
    float* Ks = sm;                    // [c][j]  64 x 128
    float* Vs = Ks + 64 * 128;         // [j][c]  128 x 64
    float* Ss = Vs + 128 * 64;         // [j][i]  128 x 128 (first 64x128 doubles as Qs)
    float* red2 = Ss + 128 * 128;      // 256 floats
    float* Qs = Ss;                    // [c][i]  64 x 128 alias
    const int tid = threadIdx.x;
    const int tx = tid & 15, ty = tid >> 4;
    const int l = blockIdx.x;
    const int h = blockIdx.y;

    const float* qbase = g_proj + (size_t)l * TD_DIM + h * DH_DIM;   // + i*L*TD
    const float* kbase = qbase + D_DIM;
    const float* vbase = qbase + 2 * D_DIM;

#pragma unroll
    for (int q = 0; q < 8; q++) {
        int id = q * 256 + tid;                 // 2048 float4 per tensor
        int r = id & 127;
        int c4 = ((id >> 7) & 15) << 2;
        float4 va = *(const float4*)(qbase + (size_t)r * L_DIM * TD_DIM + c4);
        Qs[(c4 + 0) * 128 + r] = va.x; Qs[(c4 + 1) * 128 + r] = va.y;
        Qs[(c4 + 2) * 128 + r] = va.z; Qs[(c4 + 3) * 128 + r] = va.w;
        float4 vb = *(const float4*)(kbase + (size_t)r * L_DIM * TD_DIM + c4);
        Ks[(c4 + 0) * 128 + r] = vb.x; Ks[(c4 + 1) * 128 + r] = vb.y;
        Ks[(c4 + 2) * 128 + r] = vb.z; Ks[(c4 + 3) * 128 + r] = vb.w;
        int rJ = id >> 4;
        int c42 = (id & 15) << 2;
        *(float4*)&Vs[rJ * 64 + c42] = *(const float4*)(vbase + (size_t)rJ * L_DIM * TD_DIM + c42);
    }
    __syncthreads();

    // ---- S = Q K^T : i on tx, j on ty; both operands in smem ----
    float accS[8][8];   // [jj][ii]
    {
#pragma unroll
        for (int j = 0; j < 8; j++)
#pragma unroll
            for (int i = 0; i < 8; i++) accS[j][i] = 0.0f;
#pragma unroll
        for (int c = 0; c < 64; c++) {
            float ai[8], bj[8];
            *(float4*)&ai[0] = *(const float4*)&Qs[c * 128 + tx * 8];
            *(float4*)&ai[4] = *(const float4*)&Qs[c * 128 + tx * 8 + 4];
            *(float4*)&bj[0] = *(const float4*)&Ks[c * 128 + ty * 8];
            *(float4*)&bj[4] = *(const float4*)&Ks[c * 128 + ty * 8 + 4];
#pragma unroll
            for (int j = 0; j < 8; j++)
#pragma unroll
                for (int i = 0; i < 8; i++) accS[j][i] = fmaf(ai[i], bj[j], accS[j][i]);
        }
    }
    __syncthreads();   // all Qs reads done before Ss overwrites the alias region
    {
#pragma unroll
        for (int jj = 0; jj < 8; jj++) {
            int j = ty * 8 + jj;
            float mk = mask[((size_t)h * E_DIM + j) * L_DIM + l];
#pragma unroll
            for (int i0 = 0; i0 < 8; i0 += 4) {
                float4 v;
                v.x = accS[jj][i0 + 0] + mk;
                v.y = accS[jj][i0 + 1] + mk;
                v.z = accS[jj][i0 + 2] + mk;
                v.w = accS[jj][i0 + 3] + mk;
                *(float4*)&Ss[j * 128 + tx * 8 + i0] = v;
            }
        }
    }
    __syncthreads();

    // ---- softmax over j for each i: 2 threads per i ----
    {
        const int i = tid & 127;
        const int half = tid >> 7;
        const int j0 = half * 64;
        float m = -3.4e38f;
#pragma unroll 8
        for (int j = 0; j < 64; j++) m = fmaxf(m, Ss[(j0 + j) * 128 + i]);
        red2[tid] = m;
        __syncthreads();
        m = fmaxf(red2[i], red2[i + 128]);
        float s = 0.0f;
#pragma unroll 8
        for (int j = 0; j < 64; j++) {
            float p = __expf(Ss[(j0 + j) * 128 + i] - m);
            Ss[(j0 + j) * 128 + i] = p;
            s += p;
        }
        __syncthreads();
        red2[tid] = s;
        __syncthreads();
        float inv = 1.0f / (red2[i] + red2[i + 128]);
#pragma unroll 8
        for (int j = 0; j < 64; j++) Ss[(j0 + j) * 128 + i] *= inv;
    }
    __syncthreads();

    // ---- O = P V ----
    {
        float accO[8][4];
#pragma unroll
        for (int i = 0; i < 8; i++)
#pragma unroll
            for (int c = 0; c < 4; c++) accO[i][c] = 0.0f;
#pragma unroll 4
        for (int jj = 0; jj < 128; jj++) {
            float ai[8], bc[4];
            *(float4*)&ai[0] = *(const float4*)&Ss[jj * 128 + ty * 8];
            *(float4*)&ai[4] = *(const float4*)&Ss[jj * 128 + ty * 8 + 4];
            *(float4*)&bc[0] = *(const float4*)&Vs[jj * 64 + tx * 4];
#pragma unroll
            for (int i = 0; i < 8; i++)
#pragma unroll
                for (int c = 0; c < 4; c++) accO[i][c] = fmaf(ai[i], bc[c], accO[i][c]);
        }
#pragma unroll
        for (int ii = 0; ii < 8; ii++) {
            int i = ty * 8 + ii;
            size_t off = ((size_t)i * L_DIM + l) * D_DIM + h * DH_DIM + tx * 4;
            float4 cur = *(const float4*)(out + off);
            cur.x += accO[ii][0];
            cur.y += accO[ii][1];
            cur.z += accO[ii][2];
            cur.w += accO[ii][3];
            *(float4*)(out + off) = cur;
        }
    }
}

// ---------------- launcher ----------------
extern "C" void kernel_launch(void* const* d_in, const int* in_sizes, int n_in,
                              void* d_out, int out_size) {
    const float* x     = (const float*)d_in[0];
    const float* mask  = (const float*)d_in[1];
    const float* w_row = (const float*)d_in[2];
    const float* b_row = (const float*)d_in[3];
    const float* w_col = (const float*)d_in[4];
    const float* b_col = (const float*)d_in[5];
    const float* g1    = (const float*)d_in[6];
    const float* be1   = (const float*)d_in[7];
    const float* g2    = (const float*)d_in[8];
    const float* be2   = (const float*)d_in[9];
    float* out = (float*)d_out;

    const int col_smem = COL_SMEM_FLOATS * (int)sizeof(float);  // ~100 KB
    cudaFuncSetAttribute(col_attn_kernel, cudaFuncAttributeMaxDynamicSharedMemorySize, col_smem);

    // ---- row attention stage ----
    ln_stats_kernel<<<N_ROWS, 256>>>(x);
    qkv_gemm_tc<<<dim3(TD_DIM / 128, N_ROWS / 128), 256>>>(x, w_row, b_row, g1, be1);
    scores_zero_kernel<<<(H_DIM * L_DIM * L_DIM) / 1024, 256>>>(mask);
    row_scores_tc<<<dim3(4, H_DIM, 4), 256>>>();
    row_softmax_kernel<<<H_DIM * L_DIM, 256>>>();
    row_av_kernel<<<dim3(4, H_DIM, E_DIM), 256>>>(x, out);   // out = x + row_out

    // ---- column attention stage ----
    ln_stats_kernel<<<N_ROWS, 256>>>(out);
    qkv_gemm_tc<<<dim3(TD_DIM / 128, N_ROWS / 128), 256>>>(out, w_col, b_col, g2, be2);
    col_attn_kernel<<<dim3(L_DIM, H_DIM), 256, col_smem>>>(mask, out);  // out += col_out
}

// round 7
// speedup vs baseline: 1.0822x; 1.0822x over previous
#include <cuda_runtime.h>
#include <cuda_bf16.h>
#include <cstdint>

// ---------------- problem constants ----------------
#define E_DIM 128
#define L_DIM 256
#define H_DIM 12
#define DH_DIM 64
#define D_DIM 768          // H*DH
#define TD_DIM 2304        // 3*D
#define N_ROWS 32768       // E*L
#define LN_EPS 1e-5f

// ---------------- scratch (__device__ globals; no cudaMalloc allowed) ----------------
__device__ float g_proj[(size_t)N_ROWS * TD_DIM];          // QKV projection     (~302 MB)
__device__ float g_scores[(size_t)H_DIM * L_DIM * L_DIM];  // row scores/maps    (~3 MB)
__device__ float g_lnstats[N_ROWS * 2];                    // per-row mu, rstd   (256 KB)
__device__ float g_rowmask[H_DIM * L_DIM];                 // sum_e mask[h,e,j]
__device__ unsigned g_wr_hi[(size_t)TD_DIM * D_DIM];       // w_row tf32 hi (7 MB)
__device__ unsigned g_wr_lo[(size_t)TD_DIM * D_DIM];       // w_row tf32 lo
__device__ unsigned g_wc_hi[(size_t)TD_DIM * D_DIM];       // w_col tf32 hi
__device__ unsigned g_wc_lo[(size_t)TD_DIM * D_DIM];       // w_col tf32 lo

// ---------------- tf32 helpers ----------------
__device__ __forceinline__ unsigned f2tf32(float x) {
    unsigned u;
    asm("cvt.rna.tf32.f32 %0, %1;" : "=r"(u) : "f"(x));
    return u;
}
__device__ __forceinline__ void mma_tf32(float* d, const unsigned* a, const unsigned* b) {
    asm volatile(
        "mma.sync.aligned.m16n8k8.row.col.f32.tf32.tf32.f32 "
        "{%0,%1,%2,%3}, {%4,%5,%6,%7}, {%8,%9}, {%0,%1,%2,%3};\n"
        : "+f"(d[0]), "+f"(d[1]), "+f"(d[2]), "+f"(d[3])
        : "r"(a[0]), "r"(a[1]), "r"(a[2]), "r"(a[3]), "r"(b[0]), "r"(b[1]));
}

// ---------------- reductions ----------------
__device__ __forceinline__ float warp_sum(float v) {
#pragma unroll
    for (int o = 16; o; o >>= 1) v += __shfl_xor_sync(0xffffffffu, v, o);
    return v;
}
__device__ __forceinline__ float warp_max(float v) {
#pragma unroll
    for (int o = 16; o; o >>= 1) v = fmaxf(v, __shfl_xor_sync(0xffffffffu, v, o));
    return v;
}
__device__ __forceinline__ float block_sum256(float v, float* red) {
    int lane = threadIdx.x & 31, w = threadIdx.x >> 5;
    v = warp_sum(v);
    if (lane == 0) red[w] = v;
    __syncthreads();
    if (threadIdx.x < 8) {
        float r = red[threadIdx.x];
        r += __shfl_xor_sync(0xffu, r, 4);
        r += __shfl_xor_sync(0xffu, r, 2);
        r += __shfl_xor_sync(0xffu, r, 1);
        if (threadIdx.x == 0) red[0] = r;
    }
    __syncthreads();
    float out = red[0];
    __syncthreads();
    return out;
}
__device__ __forceinline__ float block_max256(float v, float* red) {
    int lane = threadIdx.x & 31, w = threadIdx.x >> 5;
    v = warp_max(v);
    if (lane == 0) red[w] = v;
    __syncthreads();
    if (threadIdx.x < 8) {
        float r = red[threadIdx.x];
        r = fmaxf(r, __shfl_xor_sync(0xffu, r, 4));
        r = fmaxf(r, __shfl_xor_sync(0xffu, r, 2));
        r = fmaxf(r, __shfl_xor_sync(0xffu, r, 1));
        if (threadIdx.x == 0) red[0] = r;
    }
    __syncthreads();
    float out = red[0];
    __syncthreads();
    return out;
}

// ---------------- K0: split W into tf32 hi/lo (runs once per weight matrix) ----------
__global__ __launch_bounds__(256) void split_w_kernel(const float* __restrict__ W,
                                                      unsigned* __restrict__ hi,
                                                      unsigned* __restrict__ lo) {
    size_t i = ((size_t)blockIdx.x * 256 + threadIdx.x) * 4;
    float4 v = *(const float4*)(W + i);
    uint4 h, l;
    h.x = f2tf32(v.x); l.x = f2tf32(v.x - __uint_as_float(h.x));
    h.y = f2tf32(v.y); l.y = f2tf32(v.y - __uint_as_float(h.y));
    h.z = f2tf32(v.z); l.z = f2tf32(v.z - __uint_as_float(h.z));
    h.w = f2tf32(v.w); l.w = f2tf32(v.w - __uint_as_float(h.w));
    *(uint4*)(hi + i) = h;
    *(uint4*)(lo + i) = l;
}

// ---------------- K1/K6: LayerNorm stats only (mu, rstd per row) ----------------
__global__ __launch_bounds__(256) void ln_stats_kernel(const float* __restrict__ x) {
    __shared__ float red[8];
    const size_t base = (size_t)blockIdx.x * D_DIM;
    const int t = threadIdx.x;
    float v0 = x[base + t];
    float v1 = x[base + t + 256];
    float v2 = x[base + t + 512];
    float s1 = block_sum256(v0 + v1 + v2, red);
    float s2 = block_sum256(v0 * v0 + v1 * v1 + v2 * v2, red);
    const float inv_d = 1.0f / (float)D_DIM;
    float mu = s1 * inv_d;
    float var = fmaxf(s2 * inv_d - mu * mu, 0.0f);
    if (t == 0) {
        g_lnstats[blockIdx.x * 2 + 0] = mu;
        g_lnstats[blockIdx.x * 2 + 1] = rsqrtf(var + LN_EPS);
    }
}

// ---------------- K2/K7: fused LN + QKV GEMM (3xTF32; W pre-split in gmem) ----------
// C[N,2304] = LN(x)[N,768] * W[2304,768]^T + bias
// Block tile 128x128, warp tile 32x64 (8 warps). A cvt in-loop; B loaded pre-split.
__global__ __launch_bounds__(256, 2) void qkv_gemm_tc(const float* __restrict__ x,
                                                      const unsigned* __restrict__ Whi,
                                                      const unsigned* __restrict__ Wlo,
                                                      const float* __restrict__ bias,
                                                      const float* __restrict__ gamma,
                                                      const float* __restrict__ beta) {
    __shared__ float As[16][136];        // [k][m]
    __shared__ unsigned Bs_h[16][136];   // [k][n] tf32 hi
    __shared__ unsigned Bs_l[16][136];   // [k][n] tf32 lo
    __shared__ float mu_s[128], rs_s[128];
    const int tid = threadIdx.x;
    const int wid = tid >> 5, lane = tid & 31;
    const int warp_m = (wid >> 1) * 32;      // 0,32,64,96
    const int warp_n = (wid & 1) * 64;       // 0,64
    const int r = lane >> 2, c = lane & 3;
    const int m0 = blockIdx.y * 128;
    const int n0 = blockIdx.x * 128;

    if (tid < 128) {
        mu_s[tid] = g_lnstats[(m0 + tid) * 2 + 0];
        rs_s[tid] = g_lnstats[(m0 + tid) * 2 + 1];
    }

    float acc[2][8][4];
#pragma unroll
    for (int t = 0; t < 2; t++)
#pragma unroll
        for (int u = 0; u < 8; u++)
#pragma unroll
            for (int v = 0; v < 4; v++) acc[t][u][v] = 0.0f;
    __syncthreads();

    for (int k0 = 0; k0 < D_DIM; k0 += 16) {
        // ---- stage tiles (LN on A; B loads pre-split, no cvt) ----
#pragma unroll
        for (int q = 0; q < 2; q++) {
            int id = q * 256 + tid;          // 512 float4 per tile
            int rr = id >> 2;                // m or n row
            int c4 = (id & 3) << 2;          // k offset
            float4 va = *(const float4*)(x + (size_t)(m0 + rr) * D_DIM + k0 + c4);
            float4 gm = *(const float4*)(gamma + k0 + c4);
            float4 bt = *(const float4*)(beta + k0 + c4);
            float mu = mu_s[rr], rs = rs_s[rr];
            As[c4 + 0][rr] = (va.x - mu) * rs * gm.x + bt.x;
            As[c4 + 1][rr] = (va.y - mu) * rs * gm.y + bt.y;
            As[c4 + 2][rr] = (va.z - mu) * rs * gm.z + bt.z;
            As[c4 + 3][rr] = (va.w - mu) * rs * gm.w + bt.w;
            size_t woff = (size_t)(n0 + rr) * D_DIM + k0 + c4;
            uint4 wh = *(const uint4*)(Whi + woff);
            Bs_h[c4 + 0][rr] = wh.x; Bs_h[c4 + 1][rr] = wh.y;
            Bs_h[c4 + 2][rr] = wh.z; Bs_h[c4 + 3][rr] = wh.w;
            uint4 wl = *(const uint4*)(Wlo + woff);
            Bs_l[c4 + 0][rr] = wl.x; Bs_l[c4 + 1][rr] = wl.y;
            Bs_l[c4 + 2][rr] = wl.z; Bs_l[c4 + 3][rr] = wl.w;
        }
        __syncthreads();

        // ---- compute: A cvt in-loop, B pure LDS ----
#pragma unroll
        for (int k8 = 0; k8 < 16; k8 += 8) {
            unsigned Ahi[2][4], Alo[2][4];
#pragma unroll
            for (int t = 0; t < 2; t++) {
                int m = warp_m + t * 16 + r;
                float x0 = As[k8 + c][m];
                float x1 = As[k8 + c][m + 8];
                float x2 = As[k8 + c + 4][m];
                float x3 = As[k8 + c + 4][m + 8];
                Ahi[t][0] = f2tf32(x0); Alo[t][0] = f2tf32(x0 - __uint_as_float(Ahi[t][0]));
                Ahi[t][1] = f2tf32(x1); Alo[t][1] = f2tf32(x1 - __uint_as_float(Ahi[t][1]));
                Ahi[t][2] = f2tf32(x2); Alo[t][2] = f2tf32(x2 - __uint_as_float(Ahi[t][2]));
                Ahi[t][3] = f2tf32(x3); Alo[t][3] = f2tf32(x3 - __uint_as_float(Ahi[t][3]));
            }
#pragma unroll
            for (int u = 0; u < 8; u++) {
                int n = warp_n + u * 8 + r;
                unsigned Bh[2], Bl[2];
                Bh[0] = Bs_h[k8 + c][n];     Bl[0] = Bs_l[k8 + c][n];
                Bh[1] = Bs_h[k8 + 4 + c][n]; Bl[1] = Bs_l[k8 + 4 + c][n];
#pragma unroll
                for (int t = 0; t < 2; t++) {
                    mma_tf32(acc[t][u], Ahi[t], Bh);
                    mma_tf32(acc[t][u], Ahi[t], Bl);
                    mma_tf32(acc[t][u], Alo[t], Bh);
                }
            }
        }
        __syncthreads();
    }

    // ---- epilogue: bias add + store ----
#pragma unroll
    for (int t = 0; t < 2; t++) {
        int row0 = m0 + warp_m + t * 16 + r;
#pragma unroll
        for (int u = 0; u < 8; u++) {
            int col = n0 + warp_n + u * 8 + c * 2;
            float2 bz = *(const float2*)(bias + col);
            float2 v0, v1;
            v0.x = acc[t][u][0] + bz.x; v0.y = acc[t][u][1] + bz.y;
            v1.x = acc[t][u][2] + bz.x; v1.y = acc[t][u][3] + bz.y;
            *(float2*)(g_proj + (size_t)row0 * TD_DIM + col) = v0;
            *(float2*)(g_proj + (size_t)(row0 + 8) * TD_DIM + col) = v1;
        }
    }
}

// ---------------- K3a: zero scores + row mask sums ----------------
__global__ __launch_bounds__(256) void scores_zero_kernel(const float* __restrict__ mask) {
    size_t idx = (size_t)blockIdx.x * 1024 + threadIdx.x * 4;
    if (idx < (size_t)H_DIM * L_DIM * L_DIM) {
        float4 z = {0.f, 0.f, 0.f, 0.f};
        *(float4*)(g_scores + idx) = z;
    }
    int t = blockIdx.x * 256 + threadIdx.x;   // [0, H*L)
    if (t < H_DIM * L_DIM) {
        int h = t / L_DIM, j = t % L_DIM;
        float s = 0.0f;
        for (int e = 0; e < E_DIM; e++) s += mask[((size_t)h * E_DIM + e) * L_DIM + j];
        g_rowmask[t] = s;
    }
}

// ---------------- K3b: row scores (tensor cores, 3xTF32) -------------------------
// scores[h,i,j] += sum_{e,c} q[e,i,h,c] k[e,j,h,c]
// grid: (4 [2x2 ij-tiles], H, 8 [e-split]); block tile 128x128, K=16e*64c=1024.
__global__ __launch_bounds__(256, 2) void row_scores_tc() {
    __shared__ unsigned As_h[16][136], As_l[16][136];
    __shared__ unsigned Bs_h[16][136], Bs_l[16][136];
    const int tid = threadIdx.x;
    const int wid = tid >> 5, lane = tid & 31;
    const int warp_m = (wid >> 1) * 32;
    const int warp_n = (wid & 1) * 64;
    const int r = lane >> 2, c = lane & 3;
    const int it = (blockIdx.x >> 1) * 128;
    const int jt = (blockIdx.x & 1) * 128;
    const int h = blockIdx.y;
    const int e0 = blockIdx.z * 16;

    float acc[2][8][4];
#pragma unroll
    for (int t = 0; t < 2; t++)
#pragma unroll
        for (int u = 0; u < 8; u++)
#pragma unroll
            for (int v = 0; v < 4; v++) acc[t][u][v] = 0.0f;

    for (int e = e0; e < e0 + 16; e++) {
        const float* qbase = g_proj + (size_t)(e * L_DIM) * TD_DIM + h * DH_DIM;
        const float* kbase = qbase + D_DIM;
        for (int k0 = 0; k0 < DH_DIM; k0 += 16) {
#pragma unroll
            for (int q = 0; q < 2; q++) {
                int id = q * 256 + tid;
                int rr = id >> 2;
                int c4 = (id & 3) << 2;
                float4 va = *(const float4*)(qbase + (size_t)(it + rr) * TD_DIM + k0 + c4);
                unsigned hh;
                hh = f2tf32(va.x); As_h[c4 + 0][rr] = hh; As_l[c4 + 0][rr] = f2tf32(va.x - __uint_as_float(hh));
                hh = f2tf32(va.y); As_h[c4 + 1][rr] = hh; As_l[c4 + 1][rr] = f2tf32(va.y - __uint_as_float(hh));
                hh = f2tf32(va.z); As_h[c4 + 2][rr] = hh; As_l[c4 + 2][rr] = f2tf32(va.z - __uint_as_float(hh));
                hh = f2tf32(va.w); As_h[c4 + 3][rr] = hh; As_l[c4 + 3][rr] = f2tf32(va.w - __uint_as_float(hh));
                float4 vb = *(const float4*)(kbase + (size_t)(jt + rr) * TD_DIM + k0 + c4);
                hh = f2tf32(vb.x); Bs_h[c4 + 0][rr] = hh; Bs_l[c4 + 0][rr] = f2tf32(vb.x - __uint_as_float(hh));
                hh = f2tf32(vb.y); Bs_h[c4 + 1][rr] = hh; Bs_l[c4 + 1][rr] = f2tf32(vb.y - __uint_as_float(hh));
                hh = f2tf32(vb.z); Bs_h[c4 + 2][rr] = hh; Bs_l[c4 + 2][rr] = f2tf32(vb.z - __uint_as_float(hh));
                hh = f2tf32(vb.w); Bs_h[c4 + 3][rr] = hh; Bs_l[c4 + 3][rr] = f2tf32(vb.w - __uint_as_float(hh));
            }
            __syncthreads();
#pragma unroll
            for (int k8 = 0; k8 < 16; k8 += 8) {
                unsigned Ah[2][4], Al[2][4];
#pragma unroll
                for (int t = 0; t < 2; t++) {
                    int m = warp_m + t * 16 + r;
                    Ah[t][0] = As_h[k8 + c][m];     Al[t][0] = As_l[k8 + c][m];
                    Ah[t][1] = As_h[k8 + c][m + 8]; Al[t][1] = As_l[k8 + c][m + 8];
                    Ah[t][2] = As_h[k8 + c + 4][m];     Al[t][2] = As_l[k8 + c + 4][m];
                    Ah[t][3] = As_h[k8 + c + 4][m + 8]; Al[t][3] = As_l[k8 + c + 4][m + 8];
                }
#pragma unroll
                for (int u = 0; u < 8; u++) {
                    int n = warp_n + u * 8 + r;
                    unsigned Bh[2], Bl[2];
                    Bh[0] = Bs_h[k8 + c][n];     Bl[0] = Bs_l[k8 + c][n];
                    Bh[1] = Bs_h[k8 + 4 + c][n]; Bl[1] = Bs_l[k8 + 4 + c][n];
#pragma unroll
                    for (int t = 0; t < 2; t++) {
                        mma_tf32(acc[t][u], Ah[t], Bh);
                        mma_tf32(acc[t][u], Ah[t], Bl);
                        mma_tf32(acc[t][u], Al[t], Bh);
                    }
                }
            }
            __syncthreads();
        }
    }

    // ---- epilogue: atomic accumulate (split-e) ----
#pragma unroll
    for (int t = 0; t < 2; t++) {
        int row = it + warp_m + t * 16 + r;
#pragma unroll
        for (int u = 0; u < 8; u++) {
            int col = jt + warp_n + u * 8 + c * 2;
            float* p0 = &g_scores[((size_t)h * L_DIM + row) * L_DIM + col];
            atomicAdd(p0, acc[t][u][0]);
            atomicAdd(p0 + 1, acc[t][u][1]);
            float* p1 = &g_scores[((size_t)h * L_DIM + row + 8) * L_DIM + col];
            atomicAdd(p1, acc[t][u][2]);
            atomicAdd(p1 + 1, acc[t][u][3]);
        }
    }
}

// ---------------- K4: softmax over j (adds row mask on the fly) ----------------
__global__ __launch_bounds__(256) void row_softmax_kernel() {
    __shared__ float red[8];
    int h = blockIdx.x / L_DIM;
    float* row = g_scores + (size_t)blockIdx.x * L_DIM;
    float v = row[threadIdx.x] + g_rowmask[h * L_DIM + threadIdx.x];
    float m = block_max256(v, red);
    float p = __expf(v - m);
    float s = block_sum256(p, red);
    row[threadIdx.x] = p / s;
}

// ---------------- K5: row AV + residual ----------------
__global__ __launch_bounds__(256) void row_av_kernel(const float* __restrict__ x,
                                                     float* __restrict__ out) {
    __shared__ float Ms[64][64];  // [jj][i]
    __shared__ float Vs[64][64];  // [jj][c]
    const int tid = threadIdx.x;
    const int tx = tid & 15, ty = tid >> 4;
    const int it = blockIdx.x * 64;
    const int h = blockIdx.y;
    const int e = blockIdx.z;
    const float* vbase = g_proj + (size_t)(e * L_DIM) * TD_DIM + 2 * D_DIM + h * DH_DIM;
    float acc[4][4];
#pragma unroll
    for (int i = 0; i < 4; i++)
#pragma unroll
        for (int j = 0; j < 4; j++) acc[i][j] = 0.0f;

    for (int j0 = 0; j0 < L_DIM; j0 += 64) {
#pragma unroll
        for (int q = 0; q < 4; q++) {
            int id = q * 256 + tid;
            int rI = id & 63;
            int c4 = ((id >> 6) & 15) << 2;
            float4 vm = *(const float4*)(g_scores + ((size_t)h * L_DIM + it + rI) * L_DIM + j0 + c4);
            Ms[c4 + 0][rI] = vm.x; Ms[c4 + 1][rI] = vm.y; Ms[c4 + 2][rI] = vm.z; Ms[c4 + 3][rI] = vm.w;
            int rJ = id >> 4;
            int c42 = (id & 15) << 2;
            *(float4*)&Vs[rJ][c42] = *(const float4*)(vbase + (size_t)(j0 + rJ) * TD_DIM + c42);
        }
        __syncthreads();
#pragma unroll
        for (int jj = 0; jj < 64; jj++) {
            float a[4], b[4];
            *(float4*)a = *(const float4*)&Ms[jj][ty * 4];
            *(float4*)b = *(const float4*)&Vs[jj][tx * 4];
#pragma unroll
            for (int i = 0; i < 4; i++)
#pragma unroll
                for (int j = 0; j < 4; j++) acc[i][j] = fmaf(a[i], b[j], acc[i][j]);
        }
        __syncthreads();
    }
#pragma unroll
    for (int i = 0; i < 4; i++) {
        int li = it + ty * 4 + i;
        size_t off = ((size_t)(e * L_DIM + li)) * D_DIM + h * DH_DIM + tx * 4;
        float4 xr = *(const float4*)(x + off);
        float4 v;
        v.x = xr.x + acc[i][0];
        v.y = xr.y + acc[i][1];
        v.z = xr.z + acc[i][2];
        v.w = xr.w + acc[i][3];
        *(float4*)(out + off) = v;
    }
}

// ---------------- K8: fused column attention, one block per (h,l) ----------------
#define COL_SMEM_FLOATS (64 * 128 + 128 * 64 + 128 * 128 + 256)
__global__ __launch_bounds__(256) void col_attn_kernel(const float* __restrict__ mask,
                                                       float* __restrict__ out) {
    extern __shared__ float sm[];
    float* Ks = sm;                    // [c][j]  64 x 128
    float* Vs = Ks + 64 * 128;         // [j][c]  128 x 64
    float* Ss = Vs + 128 * 64;         // [j][i]  128 x 128 (first 64x128 doubles as Qs)
    float* red2 = Ss + 128 * 128;      // 256 floats
    float* Qs = Ss;                    // [c][i]  64 x 128 alias
    const int tid = threadIdx.x;
    const int tx = tid & 15, ty = tid >> 4;
    const int l = blockIdx.x;
    const int h = blockIdx.y;

    const float* qbase = g_proj + (size_t)l * TD_DIM + h * DH_DIM;   // + i*L*TD
    const float* kbase = qbase + D_DIM;
    const float* vbase = qbase + 2 * D_DIM;

#pragma unroll
    for (int q = 0; q < 8; q++) {
        int id = q * 256 + tid;                 // 2048 float4 per tensor
        int r = id & 127;
        int c4 = ((id >> 7) & 15) << 2;
        float4 va = *(const float4*)(qbase + (size_t)r * L_DIM * TD_DIM + c4);
        Qs[(c4 + 0) * 128 + r] = va.x; Qs[(c4 + 1) * 128 + r] = va.y;
        Qs[(c4 + 2) * 128 + r] = va.z; Qs[(c4 + 3) * 128 + r] = va.w;
        float4 vb = *(const float4*)(kbase + (size_t)r * L_DIM * TD_DIM + c4);
        Ks[(c4 + 0) * 128 + r] = vb.x; Ks[(c4 + 1) * 128 + r] = vb.y;
        Ks[(c4 + 2) * 128 + r] = vb.z; Ks[(c4 + 3) * 128 + r] = vb.w;
        int rJ = id >> 4;
        int c42 = (id & 15) << 2;
        *(float4*)&Vs[rJ * 64 + c42] = *(const float4*)(vbase + (size_t)rJ * L_DIM * TD_DIM + c42);
    }
    __syncthreads();

    // ---- S = Q K^T : i on tx, j on ty; both operands in smem ----
    float accS[8][8];   // [jj][ii]
    {
#pragma unroll
        for (int j = 0; j < 8; j++)
#pragma unroll
            for (int i = 0; i < 8; i++) accS[j][i] = 0.0f;
#pragma unroll
        for (int c = 0; c < 64; c++) {
            float ai[8], bj[8];
            *(float4*)&ai[0] = *(const float4*)&Qs[c * 128 + tx * 8];
            *(float4*)&ai[4] = *(const float4*)&Qs[c * 128 + tx * 8 + 4];
            *(float4*)&bj[0] = *(const float4*)&Ks[c * 128 + ty * 8];
            *(float4*)&bj[4] = *(const float4*)&Ks[c * 128 + ty * 8 + 4];
#pragma unroll
            for (int j = 0; j < 8; j++)
#pragma unroll
                for (int i = 0; i < 8; i++) accS[j][i] = fmaf(ai[i], bj[j], accS[j][i]);
        }
    }
    __syncthreads();   // all Qs reads done before Ss overwrites the alias region
    {
#pragma unroll
        for (int jj = 0; jj < 8; jj++) {
            int j = ty * 8 + jj;
            float mk = mask[((size_t)h * E_DIM + j) * L_DIM + l];
#pragma unroll
            for (int i0 = 0; i0 < 8; i0 += 4) {
                float4 v;
                v.x = accS[jj][i0 + 0] + mk;
                v.y = accS[jj][i0 + 1] + mk;
                v.z = accS[jj][i0 + 2] + mk;
                v.w = accS[jj][i0 + 3] + mk;
                *(float4*)&Ss[j * 128 + tx * 8 + i0] = v;
            }
        }
    }
    __syncthreads();

    // ---- softmax over j for each i: 2 threads per i ----
    {
        const int i = tid & 127;
        const int half = tid >> 7;
        const int j0 = half * 64;
        float m = -3.4e38f;
#pragma unroll 8
        for (int j = 0; j < 64; j++) m = fmaxf(m, Ss[(j0 + j) * 128 + i]);
        red2[tid] = m;
        __syncthreads();
        m = fmaxf(red2[i], red2[i + 128]);
        float s = 0.0f;
#pragma unroll 8
        for (int j = 0; j < 64; j++) {
            float p = __expf(Ss[(j0 + j) * 128 + i] - m);
            Ss[(j0 + j) * 128 + i] = p;
            s += p;
        }
        __syncthreads();
        red2[tid] = s;
        __syncthreads();
        float inv = 1.0f / (red2[i] + red2[i + 128]);
#pragma unroll 8
        for (int j = 0; j < 64; j++) Ss[(j0 + j) * 128 + i] *= inv;
    }
    __syncthreads();

    // ---- O = P V ----
    {
        float accO[8][4];
#pragma unroll
        for (int i = 0; i < 8; i++)
#pragma unroll
            for (int c = 0; c < 4; c++) accO[i][c] = 0.0f;
#pragma unroll 4
        for (int jj = 0; jj < 128; jj++) {
            float ai[8], bc[4];
            *(float4*)&ai[0] = *(const float4*)&Ss[jj * 128 + ty * 8];
            *(float4*)&ai[4] = *(const float4*)&Ss[jj * 128 + ty * 8 + 4];
            *(float4*)&bc[0] = *(const float4*)&Vs[jj * 64 + tx * 4];
#pragma unroll
            for (int i = 0; i < 8; i++)
#pragma unroll
                for (int c = 0; c < 4; c++) accO[i][c] = fmaf(ai[i], bc[c], accO[i][c]);
        }
#pragma unroll
        for (int ii = 0; ii < 8; ii++) {
            int i = ty * 8 + ii;
            size_t off = ((size_t)i * L_DIM + l) * D_DIM + h * DH_DIM + tx * 4;
            float4 cur = *(const float4*)(out + off);
            cur.x += accO[ii][0];
            cur.y += accO[ii][1];
            cur.z += accO[ii][2];
            cur.w += accO[ii][3];
            *(float4*)(out + off) = cur;
        }
    }
}

// ---------------- launcher ----------------
extern "C" void kernel_launch(void* const* d_in, const int* in_sizes, int n_in,
                              void* d_out, int out_size) {
    const float* x     = (const float*)d_in[0];
    const float* mask  = (const float*)d_in[1];
    const float* w_row = (const float*)d_in[2];
    const float* b_row = (const float*)d_in[3];
    const float* w_col = (const float*)d_in[4];
    const float* b_col = (const float*)d_in[5];
    const float* g1    = (const float*)d_in[6];
    const float* be1   = (const float*)d_in[7];
    const float* g2    = (const float*)d_in[8];
    const float* be2   = (const float*)d_in[9];
    float* out = (float*)d_out;

    unsigned *wr_hi, *wr_lo, *wc_hi, *wc_lo;
    cudaGetSymbolAddress((void**)&wr_hi, g_wr_hi);
    cudaGetSymbolAddress((void**)&wr_lo, g_wr_lo);
    cudaGetSymbolAddress((void**)&wc_hi, g_wc_hi);
    cudaGetSymbolAddress((void**)&wc_lo, g_wc_lo);

    const int col_smem = COL_SMEM_FLOATS * (int)sizeof(float);  // ~100 KB
    cudaFuncSetAttribute(col_attn_kernel, cudaFuncAttributeMaxDynamicSharedMemorySize, col_smem);

    const int wsplit_blocks = (TD_DIM * D_DIM) / (256 * 4);   // 1728

    // ---- row attention stage ----
    split_w_kernel<<<wsplit_blocks, 256>>>(w_row, wr_hi, wr_lo);
    split_w_kernel<<<wsplit_blocks, 256>>>(w_col, wc_hi, wc_lo);
    ln_stats_kernel<<<N_ROWS, 256>>>(x);
    qkv_gemm_tc<<<dim3(TD_DIM / 128, N_ROWS / 128), 256>>>(x, wr_hi, wr_lo, b_row, g1, be1);
    scores_zero_kernel<<<(H_DIM * L_DIM * L_DIM) / 1024, 256>>>(mask);
    row_scores_tc<<<dim3(4, H_DIM, 8), 256>>>();
    row_softmax_kernel<<<H_DIM * L_DIM, 256>>>();
    row_av_kernel<<<dim3(4, H_DIM, E_DIM), 256>>>(x, out);   // out = x + row_out

    // ---- column attention stage ----
    ln_stats_kernel<<<N_ROWS, 256>>>(out);
    qkv_gemm_tc<<<dim3(TD_DIM / 128, N_ROWS / 128), 256>>>(out, wc_hi, wc_lo, b_col, g2, be2);
    col_attn_kernel<<<dim3(L_DIM, H_DIM), 256, col_smem>>>(mask, out);  // out += col_out
}

// round 9
// speedup vs baseline: 1.2176x; 1.1252x over previous
#include <cuda_runtime.h>
#include <cuda_bf16.h>
#include <cstdint>

// ---------------- problem constants ----------------
#define E_DIM 128
#define L_DIM 256
#define H_DIM 12
#define DH_DIM 64
#define D_DIM 768          // H*DH
#define TD_DIM 2304        // 3*D
#define N_ROWS 32768       // E*L
#define LN_EPS 1e-5f

// ---------------- scratch (__device__ globals; no cudaMalloc allowed) ----------------
__device__ float g_proj[(size_t)N_ROWS * TD_DIM];          // QKV projection     (~302 MB)
__device__ float g_scores[(size_t)H_DIM * L_DIM * L_DIM];  // row scores/maps    (~3 MB)
__device__ float g_lnstats[N_ROWS * 2];                    // per-row mu, rstd   (256 KB)
__device__ float g_rowmask[H_DIM * L_DIM];                 // sum_e mask[h,e,j]
__device__ unsigned g_wr_hi[(size_t)TD_DIM * D_DIM];       // w_row tf32 hi (7 MB)
__device__ unsigned g_wr_lo[(size_t)TD_DIM * D_DIM];       // w_row tf32 lo
__device__ unsigned g_wc_hi[(size_t)TD_DIM * D_DIM];       // w_col tf32 hi
__device__ unsigned g_wc_lo[(size_t)TD_DIM * D_DIM];       // w_col tf32 lo

// ---------------- tf32 / async helpers ----------------
__device__ __forceinline__ unsigned f2tf32(float x) {
    unsigned u;
    asm("cvt.rna.tf32.f32 %0, %1;" : "=r"(u) : "f"(x));
    return u;
}
__device__ __forceinline__ void mma_tf32(float* d, const unsigned* a, const unsigned* b) {
    asm volatile(
        "mma.sync.aligned.m16n8k8.row.col.f32.tf32.tf32.f32 "
        "{%0,%1,%2,%3}, {%4,%5,%6,%7}, {%8,%9}, {%0,%1,%2,%3};\n"
        : "+f"(d[0]), "+f"(d[1]), "+f"(d[2]), "+f"(d[3])
        : "r"(a[0]), "r"(a[1]), "r"(a[2]), "r"(a[3]), "r"(b[0]), "r"(b[1]));
}
__device__ __forceinline__ void cp_async16(void* smem, const void* gmem) {
    unsigned saddr = (unsigned)__cvta_generic_to_shared(smem);
    asm volatile("cp.async.cg.shared.global [%0], [%1], 16;\n" :: "r"(saddr), "l"(gmem));
}
#define CP_COMMIT() asm volatile("cp.async.commit_group;\n" ::: "memory")
#define CP_WAIT0()  asm volatile("cp.async.wait_group 0;\n" ::: "memory")

// ---------------- reductions ----------------
__device__ __forceinline__ float warp_sum(float v) {
#pragma unroll
    for (int o = 16; o; o >>= 1) v += __shfl_xor_sync(0xffffffffu, v, o);
    return v;
}
__device__ __forceinline__ float warp_max(float v) {
#pragma unroll
    for (int o = 16; o; o >>= 1) v = fmaxf(v, __shfl_xor_sync(0xffffffffu, v, o));
    return v;
}
__device__ __forceinline__ float block_sum256(float v, float* red) {
    int lane = threadIdx.x & 31, w = threadIdx.x >> 5;
    v = warp_sum(v);
    if (lane == 0) red[w] = v;
    __syncthreads();
    if (threadIdx.x < 8) {
        float r = red[threadIdx.x];
        r += __shfl_xor_sync(0xffu, r, 4);
        r += __shfl_xor_sync(0xffu, r, 2);
        r += __shfl_xor_sync(0xffu, r, 1);
        if (threadIdx.x == 0) red[0] = r;
    }
    __syncthreads();
    float out = red[0];
    __syncthreads();
    return out;
}
__device__ __forceinline__ float block_max256(float v, float* red) {
    int lane = threadIdx.x & 31, w = threadIdx.x >> 5;
    v = warp_max(v);
    if (lane == 0) red[w] = v;
    __syncthreads();
    if (threadIdx.x < 8) {
        float r = red[threadIdx.x];
        r = fmaxf(r, __shfl_xor_sync(0xffu, r, 4));
        r = fmaxf(r, __shfl_xor_sync(0xffu, r, 2));
        r = fmaxf(r, __shfl_xor_sync(0xffu, r, 1));
        if (threadIdx.x == 0) red[0] = r;
    }
    __syncthreads();
    float out = red[0];
    __syncthreads();
    return out;
}

// ---------------- K0: split W into tf32 hi/lo (runs once per weight matrix) ----------
__global__ __launch_bounds__(256) void split_w_kernel(const float* __restrict__ W,
                                                      unsigned* __restrict__ hi,
                                                      unsigned* __restrict__ lo) {
    size_t i = ((size_t)blockIdx.x * 256 + threadIdx.x) * 4;
    float4 v = *(const float4*)(W + i);
    uint4 h, l;
    h.x = f2tf32(v.x); l.x = f2tf32(v.x - __uint_as_float(h.x));
    h.y = f2tf32(v.y); l.y = f2tf32(v.y - __uint_as_float(h.y));
    h.z = f2tf32(v.z); l.z = f2tf32(v.z - __uint_as_float(h.z));
    h.w = f2tf32(v.w); l.w = f2tf32(v.w - __uint_as_float(h.w));
    *(uint4*)(hi + i) = h;
    *(uint4*)(lo + i) = l;
}

// ---------------- K1/K6: LayerNorm stats only (mu, rstd per row) ----------------
__global__ __launch_bounds__(256) void ln_stats_kernel(const float* __restrict__ x) {
    __shared__ float red[8];
    const size_t base = (size_t)blockIdx.x * D_DIM;
    const int t = threadIdx.x;
    float v0 = x[base + t];
    float v1 = x[base + t + 256];
    float v2 = x[base + t + 512];
    float s1 = block_sum256(v0 + v1 + v2, red);
    float s2 = block_sum256(v0 * v0 + v1 * v1 + v2 * v2, red);
    const float inv_d = 1.0f / (float)D_DIM;
    float mu = s1 * inv_d;
    float var = fmaxf(s2 * inv_d - mu * mu, 0.0f);
    if (t == 0) {
        g_lnstats[blockIdx.x * 2 + 0] = mu;
        g_lnstats[blockIdx.x * 2 + 1] = rsqrtf(var + LN_EPS);
    }
}

// ---------------- K2/K7: fused LN + QKV GEMM (3xTF32, double-buffered pipeline) ------
// C[N,2304] = LN(x)[N,768] * W[2304,768]^T + bias
// Block tile 128x128, warp tile 32x64 (8 warps).
// Dynamic smem (64 KB): As[2][16][136] f32 | Bsh[2][128][20] u32 | Bsl[2][128][20] u32
//                       | mu[128] | rs[128] | gs[768] | bs[768]
#define QKV_AS_STRIDE 136
#define QKV_AS_TILE   (16 * QKV_AS_STRIDE)        // 2176
#define QKV_BS_STRIDE 20
#define QKV_BS_TILE   (128 * QKV_BS_STRIDE)       // 2560
#define QKV_SMEM_FLOATS (2 * QKV_AS_TILE + 4 * QKV_BS_TILE + 128 + 128 + 768 + 768) // 16384
__global__ __launch_bounds__(256, 2) void qkv_gemm_tc(const float* __restrict__ x,
                                                      const unsigned* __restrict__ Whi,
                                                      const unsigned* __restrict__ Wlo,
                                                      const float* __restrict__ bias,
                                                      const float* __restrict__ gamma,
                                                      const float* __restrict__ beta) {
    extern __shared__ float sm[];
    float* As = sm;                                   // 2 tiles
    unsigned* Bsh = (unsigned*)(sm + 2 * QKV_AS_TILE);
    unsigned* Bsl = Bsh + 2 * QKV_BS_TILE;
    float* mu_s = (float*)(Bsl + 2 * QKV_BS_TILE);
    float* rs_s = mu_s + 128;
    float* gs = rs_s + 128;
    float* bs = gs + 768;

    const int tid = threadIdx.x;
    const int wid = tid >> 5, lane = tid & 31;
    const int warp_m = (wid >> 1) * 32;      // 0,32,64,96
    const int warp_n = (wid & 1) * 64;       // 0,64
    const int r = lane >> 2, c = lane & 3;
    const int m0 = blockIdx.y * 128;
    const int n0 = blockIdx.x * 128;

    // thread's staging coordinates (2 chunks per tile)
    const int rr0 = tid >> 2;                 // 0..63
    const int rr1 = rr0 + 64;                 // 64..127
    const int cc = (tid & 3) << 2;            // 0,4,8,12

    // ---- prologue: constants ----
    if (tid < 128) {
        mu_s[tid] = g_lnstats[(m0 + tid) * 2 + 0];
        rs_s[tid] = g_lnstats[(m0 + tid) * 2 + 1];
    }
    for (int i = tid; i < 768; i += 256) {
        gs[i] = gamma[i];
        bs[i] = beta[i];
    }
    __syncthreads();

    float acc[2][8][4];
#pragma unroll
    for (int t = 0; t < 2; t++)
#pragma unroll
        for (int u = 0; u < 8; u++)
#pragma unroll
            for (int v = 0; v < 4; v++) acc[t][u][v] = 0.0f;

    // ---- prologue: stage tile 0 ----
    {
        // A: LDG + LN transform + transposed STS
#pragma unroll
        for (int q = 0; q < 2; q++) {
            int rr = q ? rr1 : rr0;
            float4 va = *(const float4*)(x + (size_t)(m0 + rr) * D_DIM + cc);
            float mu = mu_s[rr], rs = rs_s[rr];
            As[(cc + 0) * QKV_AS_STRIDE + rr] = (va.x - mu) * rs * gs[cc + 0] + bs[cc + 0];
            As[(cc + 1) * QKV_AS_STRIDE + rr] = (va.y - mu) * rs * gs[cc + 1] + bs[cc + 1];
            As[(cc + 2) * QKV_AS_STRIDE + rr] = (va.z - mu) * rs * gs[cc + 2] + bs[cc + 2];
            As[(cc + 3) * QKV_AS_STRIDE + rr] = (va.w - mu) * rs * gs[cc + 3] + bs[cc + 3];
        }
        // B: async copy (raw, pre-split)
#pragma unroll
        for (int q = 0; q < 2; q++) {
            int rr = q ? rr1 : rr0;
            size_t woff = (size_t)(n0 + rr) * D_DIM + cc;
            cp_async16(&Bsh[rr * QKV_BS_STRIDE + cc], Whi + woff);
            cp_async16(&Bsl[rr * QKV_BS_STRIDE + cc], Wlo + woff);
        }
        CP_COMMIT();
    }

    // ---- pipelined main loop over 48 k-tiles ----
    for (int kt = 0; kt < 48; kt++) {
        const int b = kt & 1;
        CP_WAIT0();
        __syncthreads();   // tile kt fully visible (A stored end of kt-1, B landed)

        const bool has_next = (kt < 47);
        const int k0n = (kt + 1) * 16;
        float4 va_n[2];
        if (has_next) {
            // prefetch A (regs) + issue B cp.async into buffer b^1
#pragma unroll
            for (int q = 0; q < 2; q++) {
                int rr = q ? rr1 : rr0;
                va_n[q] = *(const float4*)(x + (size_t)(m0 + rr) * D_DIM + k0n + cc);
                size_t woff = (size_t)(n0 + rr) * D_DIM + k0n + cc;
                cp_async16(&Bsh[(b ^ 1) * QKV_BS_TILE + rr * QKV_BS_STRIDE + cc], Whi + woff);
                cp_async16(&Bsl[(b ^ 1) * QKV_BS_TILE + rr * QKV_BS_STRIDE + cc], Wlo + woff);
            }
            CP_COMMIT();
        }

        // ---- compute on buffer b ----
        const float* Ab = As + b * QKV_AS_TILE;
        const unsigned* Bhb = Bsh + b * QKV_BS_TILE;
        const unsigned* Blb = Bsl + b * QKV_BS_TILE;
#pragma unroll
        for (int k8 = 0; k8 < 16; k8 += 8) {
            unsigned Ahi[2][4], Alo[2][4];
#pragma unroll
            for (int t = 0; t < 2; t++) {
                int m = warp_m + t * 16 + r;
                float x0 = Ab[(k8 + c) * QKV_AS_STRIDE + m];
                float x1 = Ab[(k8 + c) * QKV_AS_STRIDE + m + 8];
                float x2 = Ab[(k8 + c + 4) * QKV_AS_STRIDE + m];
                float x3 = Ab[(k8 + c + 4) * QKV_AS_STRIDE + m + 8];
                Ahi[t][0] = f2tf32(x0); Alo[t][0] = f2tf32(x0 - __uint_as_float(Ahi[t][0]));
                Ahi[t][1] = f2tf32(x1); Alo[t][1] = f2tf32(x1 - __uint_as_float(Ahi[t][1]));
                Ahi[t][2] = f2tf32(x2); Alo[t][2] = f2tf32(x2 - __uint_as_float(Ahi[t][2]));
                Ahi[t][3] = f2tf32(x3); Alo[t][3] = f2tf32(x3 - __uint_as_float(Ahi[t][3]));
            }
#pragma unroll
            for (int u = 0; u < 8; u++) {
                int n = warp_n + u * 8 + r;
                unsigned Bh[2], Bl[2];
                Bh[0] = Bhb[n * QKV_BS_STRIDE + k8 + c];
                Bh[1] = Bhb[n * QKV_BS_STRIDE + k8 + 4 + c];
                Bl[0] = Blb[n * QKV_BS_STRIDE + k8 + c];
                Bl[1] = Blb[n * QKV_BS_STRIDE + k8 + 4 + c];
#pragma unroll
                for (int t = 0; t < 2; t++) {
                    mma_tf32(acc[t][u], Ahi[t], Bh);
                    mma_tf32(acc[t][u], Ahi[t], Bl);
                    mma_tf32(acc[t][u], Alo[t], Bh);
                }
            }
        }

        // ---- store prefetched A into buffer b^1 ----
        if (has_next) {
            float* An = As + (b ^ 1) * QKV_AS_TILE;
#pragma unroll
            for (int q = 0; q < 2; q++) {
                int rr = q ? rr1 : rr0;
                float mu = mu_s[rr], rs = rs_s[rr];
                float4 va = va_n[q];
                An[(cc + 0) * QKV_AS_STRIDE + rr] = (va.x - mu) * rs * gs[k0n + cc + 0] + bs[k0n + cc + 0];
                An[(cc + 1) * QKV_AS_STRIDE + rr] = (va.y - mu) * rs * gs[k0n + cc + 1] + bs[k0n + cc + 1];
                An[(cc + 2) * QKV_AS_STRIDE + rr] = (va.z - mu) * rs * gs[k0n + cc + 2] + bs[k0n + cc + 2];
                An[(cc + 3) * QKV_AS_STRIDE + rr] = (va.w - mu) * rs * gs[k0n + cc + 3] + bs[k0n + cc + 3];
            }
        }
    }

    // ---- epilogue: bias add + store ----
#pragma unroll
    for (int t = 0; t < 2; t++) {
        int row0 = m0 + warp_m + t * 16 + r;
#pragma unroll
        for (int u = 0; u < 8; u++) {
            int col = n0 + warp_n + u * 8 + c * 2;
            float2 bz = *(const float2*)(bias + col);
            float2 v0, v1;
            v0.x = acc[t][u][0] + bz.x; v0.y = acc[t][u][1] + bz.y;
            v1.x = acc[t][u][2] + bz.x; v1.y = acc[t][u][3] + bz.y;
            *(float2*)(g_proj + (size_t)row0 * TD_DIM + col) = v0;
            *(float2*)(g_proj + (size_t)(row0 + 8) * TD_DIM + col) = v1;
        }
    }
}

// ---------------- K3a: zero scores + row mask sums ----------------
__global__ __launch_bounds__(256) void scores_zero_kernel(const float* __restrict__ mask) {
    size_t idx = (size_t)blockIdx.x * 1024 + threadIdx.x * 4;
    if (idx < (size_t)H_DIM * L_DIM * L_DIM) {
        float4 z = {0.f, 0.f, 0.f, 0.f};
        *(float4*)(g_scores + idx) = z;
    }
    int t = blockIdx.x * 256 + threadIdx.x;   // [0, H*L)
    if (t < H_DIM * L_DIM) {
        int h = t / L_DIM, j = t % L_DIM;
        float s = 0.0f;
        for (int e = 0; e < E_DIM; e++) s += mask[((size_t)h * E_DIM + e) * L_DIM + j];
        g_rowmask[t] = s;
    }
}

// ---------------- K3b: row scores (tensor cores, 3xTF32) -------------------------
__global__ __launch_bounds__(256, 2) void row_scores_tc() {
    __shared__ unsigned As_h[16][136], As_l[16][136];
    __shared__ unsigned Bs_h[16][136], Bs_l[16][136];
    const int tid = threadIdx.x;
    const int wid = tid >> 5, lane = tid & 31;
    const int warp_m = (wid >> 1) * 32;
    const int warp_n = (wid & 1) * 64;
    const int r = lane >> 2, c = lane & 3;
    const int it = (blockIdx.x >> 1) * 128;
    const int jt = (blockIdx.x & 1) * 128;
    const int h = blockIdx.y;
    const int e0 = blockIdx.z * 16;

    float acc[2][8][4];
#pragma unroll
    for (int t = 0; t < 2; t++)
#pragma unroll
        for (int u = 0; u < 8; u++)
#pragma unroll
            for (int v = 0; v < 4; v++) acc[t][u][v] = 0.0f;

    for (int e = e0; e < e0 + 16; e++) {
        const float* qbase = g_proj + (size_t)(e * L_DIM) * TD_DIM + h * DH_DIM;
        const float* kbase = qbase + D_DIM;
        for (int k0 = 0; k0 < DH_DIM; k0 += 16) {
#pragma unroll
            for (int q = 0; q < 2; q++) {
                int id = q * 256 + tid;
                int rr = id >> 2;
                int c4 = (id & 3) << 2;
                float4 va = *(const float4*)(qbase + (size_t)(it + rr) * TD_DIM + k0 + c4);
                unsigned hh;
                hh = f2tf32(va.x); As_h[c4 + 0][rr] = hh; As_l[c4 + 0][rr] = f2tf32(va.x - __uint_as_float(hh));
                hh = f2tf32(va.y); As_h[c4 + 1][rr] = hh; As_l[c4 + 1][rr] = f2tf32(va.y - __uint_as_float(hh));
                hh = f2tf32(va.z); As_h[c4 + 2][rr] = hh; As_l[c4 + 2][rr] = f2tf32(va.z - __uint_as_float(hh));
                hh = f2tf32(va.w); As_h[c4 + 3][rr] = hh; As_l[c4 + 3][rr] = f2tf32(va.w - __uint_as_float(hh));
                float4 vb = *(const float4*)(kbase + (size_t)(jt + rr) * TD_DIM + k0 + c4);
                hh = f2tf32(vb.x); Bs_h[c4 + 0][rr] = hh; Bs_l[c4 + 0][rr] = f2tf32(vb.x - __uint_as_float(hh));
                hh = f2tf32(vb.y); Bs_h[c4 + 1][rr] = hh; Bs_l[c4 + 1][rr] = f2tf32(vb.y - __uint_as_float(hh));
                hh = f2tf32(vb.z); Bs_h[c4 + 2][rr] = hh; Bs_l[c4 + 2][rr] = f2tf32(vb.z - __uint_as_float(hh));
                hh = f2tf32(vb.w); Bs_h[c4 + 3][rr] = hh; Bs_l[c4 + 3][rr] = f2tf32(vb.w - __uint_as_float(hh));
            }
            __syncthreads();
#pragma unroll
            for (int k8 = 0; k8 < 16; k8 += 8) {
                unsigned Ah[2][4], Al[2][4];
#pragma unroll
                for (int t = 0; t < 2; t++) {
                    int m = warp_m + t * 16 + r;
                    Ah[t][0] = As_h[k8 + c][m];     Al[t][0] = As_l[k8 + c][m];
                    Ah[t][1] = As_h[k8 + c][m + 8]; Al[t][1] = As_l[k8 + c][m + 8];
                    Ah[t][2] = As_h[k8 + c + 4][m];     Al[t][2] = As_l[k8 + c + 4][m];
                    Ah[t][3] = As_h[k8 + c + 4][m + 8]; Al[t][3] = As_l[k8 + c + 4][m + 8];
                }
#pragma unroll
                for (int u = 0; u < 8; u++) {
                    int n = warp_n + u * 8 + r;
                    unsigned Bh[2], Bl[2];
                    Bh[0] = Bs_h[k8 + c][n];     Bl[0] = Bs_l[k8 + c][n];
                    Bh[1] = Bs_h[k8 + 4 + c][n]; Bl[1] = Bs_l[k8 + 4 + c][n];
#pragma unroll
                    for (int t = 0; t < 2; t++) {
                        mma_tf32(acc[t][u], Ah[t], Bh);
                        mma_tf32(acc[t][u], Ah[t], Bl);
                        mma_tf32(acc[t][u], Al[t], Bh);
                    }
                }
            }
            __syncthreads();
        }
    }

#pragma unroll
    for (int t = 0; t < 2; t++) {
        int row = it + warp_m + t * 16 + r;
#pragma unroll
        for (int u = 0; u < 8; u++) {
            int col = jt + warp_n + u * 8 + c * 2;
            float* p0 = &g_scores[((size_t)h * L_DIM + row) * L_DIM + col];
            atomicAdd(p0, acc[t][u][0]);
            atomicAdd(p0 + 1, acc[t][u][1]);
            float* p1 = &g_scores[((size_t)h * L_DIM + row + 8) * L_DIM + col];
            atomicAdd(p1, acc[t][u][2]);
            atomicAdd(p1 + 1, acc[t][u][3]);
        }
    }
}

// ---------------- K4: softmax over j (adds row mask on the fly) ----------------
__global__ __launch_bounds__(256) void row_softmax_kernel() {
    __shared__ float red[8];
    int h = blockIdx.x / L_DIM;
    float* row = g_scores + (size_t)blockIdx.x * L_DIM;
    float v = row[threadIdx.x] + g_rowmask[h * L_DIM + threadIdx.x];
    float m = block_max256(v, red);
    float p = __expf(v - m);
    float s = block_sum256(p, red);
    row[threadIdx.x] = p / s;
}

// ---------------- K5: row AV + residual ----------------
__global__ __launch_bounds__(256) void row_av_kernel(const float* __restrict__ x,
                                                     float* __restrict__ out) {
    __shared__ float Ms[64][64];  // [jj][i]
    __shared__ float Vs[64][64];  // [jj][c]
    const int tid = threadIdx.x;
    const int tx = tid & 15, ty = tid >> 4;
    const int it = blockIdx.x * 64;
    const int h = blockIdx.y;
    const int e = blockIdx.z;
    const float* vbase = g_proj + (size_t)(e * L_DIM) * TD_DIM + 2 * D_DIM + h * DH_DIM;
    float acc[4][4];
#pragma unroll
    for (int i = 0; i < 4; i++)
#pragma unroll
        for (int j = 0; j < 4; j++) acc[i][j] = 0.0f;

    for (int j0 = 0; j0 < L_DIM; j0 += 64) {
#pragma unroll
        for (int q = 0; q < 4; q++) {
            int id = q * 256 + tid;
            int rI = id & 63;
            int c4 = ((id >> 6) & 15) << 2;
            float4 vm = *(const float4*)(g_scores + ((size_t)h * L_DIM + it + rI) * L_DIM + j0 + c4);
            Ms[c4 + 0][rI] = vm.x; Ms[c4 + 1][rI] = vm.y; Ms[c4 + 2][rI] = vm.z; Ms[c4 + 3][rI] = vm.w;
            int rJ = id >> 4;
            int c42 = (id & 15) << 2;
            *(float4*)&Vs[rJ][c42] = *(const float4*)(vbase + (size_t)(j0 + rJ) * TD_DIM + c42);
        }
        __syncthreads();
#pragma unroll
        for (int jj = 0; jj < 64; jj++) {
            float a[4], b[4];
            *(float4*)a = *(const float4*)&Ms[jj][ty * 4];
            *(float4*)b = *(const float4*)&Vs[jj][tx * 4];
#pragma unroll
            for (int i = 0; i < 4; i++)
#pragma unroll
                for (int j = 0; j < 4; j++) acc[i][j] = fmaf(a[i], b[j], acc[i][j]);
        }
        __syncthreads();
    }
#pragma unroll
    for (int i = 0; i < 4; i++) {
        int li = it + ty * 4 + i;
        size_t off = ((size_t)(e * L_DIM + li)) * D_DIM + h * DH_DIM + tx * 4;
        float4 xr = *(const float4*)(x + off);
        float4 v;
        v.x = xr.x + acc[i][0];
        v.y = xr.y + acc[i][1];
        v.z = xr.z + acc[i][2];
        v.w = xr.w + acc[i][3];
        *(float4*)(out + off) = v;
    }
}

// ---------------- K8: fused column attention, one block per (h,l) ----------------
#define COL_SMEM_FLOATS (64 * 128 + 128 * 64 + 128 * 128 + 256)
__global__ __launch_bounds__(256) void col_attn_kernel(const float* __restrict__ mask,
                                                       float* __restrict__ out) {
    extern __shared__ float sm[];
    float* Ks = sm;                    // [c][j]  64 x 128
    float* Vs = Ks + 64 * 128;         // [j][c]  128 x 64
    float* Ss = Vs + 128 * 64;         // [j][i]  128 x 128 (first 64x128 doubles as Qs)
    float* red2 = Ss + 128 * 128;      // 256 floats
    float* Qs = Ss;                    // [c][i]  64 x 128 alias
    const int tid = threadIdx.x;
    const int tx = tid & 15, ty = tid >> 4;
    const int l = blockIdx.x;
    const int h = blockIdx.y;

    const float* qbase = g_proj + (size_t)l * TD_DIM + h * DH_DIM;   // + i*L*TD
    const float* kbase = qbase + D_DIM;
    const float* vbase = qbase + 2 * D_DIM;

#pragma unroll
    for (int q = 0; q < 8; q++) {
        int id = q * 256 + tid;                 // 2048 float4 per tensor
        int r = id & 127;
        int c4 = ((id >> 7) & 15) << 2;
        float4 va = *(const float4*)(qbase + (size_t)r * L_DIM * TD_DIM + c4);
        Qs[(c4 + 0) * 128 + r] = va.x; Qs[(c4 + 1) * 128 + r] = va.y;
        Qs[(c4 + 2) * 128 + r] = va.z; Qs[(c4 + 3) * 128 + r] = va.w;
        float4 vb = *(const float4*)(kbase + (size_t)r * L_DIM * TD_DIM + c4);
        Ks[(c4 + 0) * 128 + r] = vb.x; Ks[(c4 + 1) * 128 + r] = vb.y;
        Ks[(c4 + 2) * 128 + r] = vb.z; Ks[(c4 + 3) * 128 + r] = vb.w;
        int rJ = id >> 4;
        int c42 = (id & 15) << 2;
        *(float4*)&Vs[rJ * 64 + c42] = *(const float4*)(vbase + (size_t)rJ * L_DIM * TD_DIM + c42);
    }
    __syncthreads();

    float accS[8][8];   // [jj][ii]
    {
#pragma unroll
        for (int j = 0; j < 8; j++)
#pragma unroll
            for (int i = 0; i < 8; i++) accS[j][i] = 0.0f;
#pragma unroll
        for (int c = 0; c < 64; c++) {
            float ai[8], bj[8];
            *(float4*)&ai[0] = *(const float4*)&Qs[c * 128 + tx * 8];
            *(float4*)&ai[4] = *(const float4*)&Qs[c * 128 + tx * 8 + 4];
            *(float4*)&bj[0] = *(const float4*)&Ks[c * 128 + ty * 8];
            *(float4*)&bj[4] = *(const float4*)&Ks[c * 128 + ty * 8 + 4];
#pragma unroll
            for (int j = 0; j < 8; j++)
#pragma unroll
                for (int i = 0; i < 8; i++) accS[j][i] = fmaf(ai[i], bj[j], accS[j][i]);
        }
    }
    __syncthreads();   // all Qs reads done before Ss overwrites the alias region
    {
#pragma unroll
        for (int jj = 0; jj < 8; jj++) {
            int j = ty * 8 + jj;
            float mk = mask[((size_t)h * E_DIM + j) * L_DIM + l];
#pragma unroll
            for (int i0 = 0; i0 < 8; i0 += 4) {
                float4 v;
                v.x = accS[jj][i0 + 0] + mk;
                v.y = accS[jj][i0 + 1] + mk;
                v.z = accS[jj][i0 + 2] + mk;
                v.w = accS[jj][i0 + 3] + mk;
                *(float4*)&Ss[j * 128 + tx * 8 + i0] = v;
            }
        }
    }
    __syncthreads();

    {
        const int i = tid & 127;
        const int half = tid >> 7;
        const int j0 = half * 64;
        float m = -3.4e38f;
#pragma unroll 8
        for (int j = 0; j < 64; j++) m = fmaxf(m, Ss[(j0 + j) * 128 + i]);
        red2[tid] = m;
        __syncthreads();
        m = fmaxf(red2[i], red2[i + 128]);
        float s = 0.0f;
#pragma unroll 8
        for (int j = 0; j < 64; j++) {
            float p = __expf(Ss[(j0 + j) * 128 + i] - m);
            Ss[(j0 + j) * 128 + i] = p;
            s += p;
        }
        __syncthreads();
        red2[tid] = s;
        __syncthreads();
        float inv = 1.0f / (red2[i] + red2[i + 128]);
#pragma unroll 8
        for (int j = 0; j < 64; j++) Ss[(j0 + j) * 128 + i] *= inv;
    }
    __syncthreads();

    {
        float accO[8][4];
#pragma unroll
        for (int i = 0; i < 8; i++)
#pragma unroll
            for (int c = 0; c < 4; c++) accO[i][c] = 0.0f;
#pragma unroll 4
        for (int jj = 0; jj < 128; jj++) {
            float ai[8], bc[4];
            *(float4*)&ai[0] = *(const float4*)&Ss[jj * 128 + ty * 8];
            *(float4*)&ai[4] = *(const float4*)&Ss[jj * 128 + ty * 8 + 4];
            *(float4*)&bc[0] = *(const float4*)&Vs[jj * 64 + tx * 4];
#pragma unroll
            for (int i = 0; i < 8; i++)
#pragma unroll
                for (int c = 0; c < 4; c++) accO[i][c] = fmaf(ai[i], bc[c], accO[i][c]);
        }
#pragma unroll
        for (int ii = 0; ii < 8; ii++) {
            int i = ty * 8 + ii;
            size_t off = ((size_t)i * L_DIM + l) * D_DIM + h * DH_DIM + tx * 4;
            float4 cur = *(const float4*)(out + off);
            cur.x += accO[ii][0];
            cur.y += accO[ii][1];
            cur.z += accO[ii][2];
            cur.w += accO[ii][3];
            *(float4*)(out + off) = cur;
        }
    }
}

// ---------------- launcher ----------------
extern "C" void kernel_launch(void* const* d_in, const int* in_sizes, int n_in,
                              void* d_out, int out_size) {
    const float* x     = (const float*)d_in[0];
    const float* mask  = (const float*)d_in[1];
    const float* w_row = (const float*)d_in[2];
    const float* b_row = (const float*)d_in[3];
    const float* w_col = (const float*)d_in[4];
    const float* b_col = (const float*)d_in[5];
    const float* g1    = (const float*)d_in[6];
    const float* be1   = (const float*)d_in[7];
    const float* g2    = (const float*)d_in[8];
    const float* be2   = (const float*)d_in[9];
    float* out = (float*)d_out;

    unsigned *wr_hi, *wr_lo, *wc_hi, *wc_lo;
    cudaGetSymbolAddress((void**)&wr_hi, g_wr_hi);
    cudaGetSymbolAddress((void**)&wr_lo, g_wr_lo);
    cudaGetSymbolAddress((void**)&wc_hi, g_wc_hi);
    cudaGetSymbolAddress((void**)&wc_lo, g_wc_lo);

    const int col_smem = COL_SMEM_FLOATS * (int)sizeof(float);   // ~100 KB
    const int qkv_smem = QKV_SMEM_FLOATS * (int)sizeof(float);   // 64 KB
    cudaFuncSetAttribute(col_attn_kernel, cudaFuncAttributeMaxDynamicSharedMemorySize, col_smem);
    cudaFuncSetAttribute(qkv_gemm_tc, cudaFuncAttributeMaxDynamicSharedMemorySize, qkv_smem);

    const int wsplit_blocks = (TD_DIM * D_DIM) / (256 * 4);   // 1728

    // ---- row attention stage ----
    split_w_kernel<<<wsplit_blocks, 256>>>(w_row, wr_hi, wr_lo);
    split_w_kernel<<<wsplit_blocks, 256>>>(w_col, wc_hi, wc_lo);
    ln_stats_kernel<<<N_ROWS, 256>>>(x);
    qkv_gemm_tc<<<dim3(TD_DIM / 128, N_ROWS / 128), 256, qkv_smem>>>(x, wr_hi, wr_lo, b_row, g1, be1);
    scores_zero_kernel<<<(H_DIM * L_DIM * L_DIM) / 1024, 256>>>(mask);
    row_scores_tc<<<dim3(4, H_DIM, 8), 256>>>();
    row_softmax_kernel<<<H_DIM * L_DIM, 256>>>();
    row_av_kernel<<<dim3(4, H_DIM, E_DIM), 256>>>(x, out);   // out = x + row_out

    // ---- column attention stage ----
    ln_stats_kernel<<<N_ROWS, 256>>>(out);
    qkv_gemm_tc<<<dim3(TD_DIM / 128, N_ROWS / 128), 256, qkv_smem>>>(out, wc_hi, wc_lo, b_col, g2, be2);
    col_attn_kernel<<<dim3(L_DIM, H_DIM), 256, col_smem>>>(mask, out);  // out += col_out
}

// round 10
// speedup vs baseline: 1.2429x; 1.0208x over previous
#include <cuda_runtime.h>
#include <cuda_bf16.h>
#include <cstdint>

// ---------------- problem constants ----------------
#define E_DIM 128
#define L_DIM 256
#define H_DIM 12
#define DH_DIM 64
#define D_DIM 768          // H*DH
#define TD_DIM 2304        // 3*D
#define N_ROWS 32768       // E*L
#define LN_EPS 1e-5f

// ---------------- scratch (__device__ globals; no cudaMalloc allowed) ----------------
__device__ float g_proj[(size_t)N_ROWS * TD_DIM];          // QKV projection     (~302 MB)
__device__ float g_scores[(size_t)H_DIM * L_DIM * L_DIM];  // row scores/maps    (~3 MB)
__device__ float g_lnstats[N_ROWS * 2];                    // per-row mu, rstd   (256 KB)
__device__ float g_rowmask[H_DIM * L_DIM];                 // sum_e mask[h,e,j]
__device__ unsigned g_wr_hi[(size_t)TD_DIM * D_DIM];       // w_row tf32 hi (7 MB)
__device__ unsigned g_wr_lo[(size_t)TD_DIM * D_DIM];       // w_row tf32 lo
__device__ unsigned g_wc_hi[(size_t)TD_DIM * D_DIM];       // w_col tf32 hi
__device__ unsigned g_wc_lo[(size_t)TD_DIM * D_DIM];       // w_col tf32 lo

// ---------------- tf32 / async helpers ----------------
__device__ __forceinline__ unsigned f2tf32(float x) {
    unsigned u;
    asm("cvt.rna.tf32.f32 %0, %1;" : "=r"(u) : "f"(x));
    return u;
}
__device__ __forceinline__ void mma_tf32(float* d, const unsigned* a, const unsigned* b) {
    asm volatile(
        "mma.sync.aligned.m16n8k8.row.col.f32.tf32.tf32.f32 "
        "{%0,%1,%2,%3}, {%4,%5,%6,%7}, {%8,%9}, {%0,%1,%2,%3};\n"
        : "+f"(d[0]), "+f"(d[1]), "+f"(d[2]), "+f"(d[3])
        : "r"(a[0]), "r"(a[1]), "r"(a[2]), "r"(a[3]), "r"(b[0]), "r"(b[1]));
}
__device__ __forceinline__ void cp_async16(void* smem, const void* gmem) {
    unsigned saddr = (unsigned)__cvta_generic_to_shared(smem);
    asm volatile("cp.async.cg.shared.global [%0], [%1], 16;\n" :: "r"(saddr), "l"(gmem));
}
#define CP_COMMIT() asm volatile("cp.async.commit_group;\n" ::: "memory")
#define CP_WAIT0()  asm volatile("cp.async.wait_group 0;\n" ::: "memory")

// ---------------- reductions ----------------
__device__ __forceinline__ float warp_sum(float v) {
#pragma unroll
    for (int o = 16; o; o >>= 1) v += __shfl_xor_sync(0xffffffffu, v, o);
    return v;
}
__device__ __forceinline__ float warp_max(float v) {
#pragma unroll
    for (int o = 16; o; o >>= 1) v = fmaxf(v, __shfl_xor_sync(0xffffffffu, v, o));
    return v;
}
__device__ __forceinline__ float block_sum256(float v, float* red) {
    int lane = threadIdx.x & 31, w = threadIdx.x >> 5;
    v = warp_sum(v);
    if (lane == 0) red[w] = v;
    __syncthreads();
    if (threadIdx.x < 8) {
        float r = red[threadIdx.x];
        r += __shfl_xor_sync(0xffu, r, 4);
        r += __shfl_xor_sync(0xffu, r, 2);
        r += __shfl_xor_sync(0xffu, r, 1);
        if (threadIdx.x == 0) red[0] = r;
    }
    __syncthreads();
    float out = red[0];
    __syncthreads();
    return out;
}
__device__ __forceinline__ float block_max256(float v, float* red) {
    int lane = threadIdx.x & 31, w = threadIdx.x >> 5;
    v = warp_max(v);
    if (lane == 0) red[w] = v;
    __syncthreads();
    if (threadIdx.x < 8) {
        float r = red[threadIdx.x];
        r = fmaxf(r, __shfl_xor_sync(0xffu, r, 4));
        r = fmaxf(r, __shfl_xor_sync(0xffu, r, 2));
        r = fmaxf(r, __shfl_xor_sync(0xffu, r, 1));
        if (threadIdx.x == 0) red[0] = r;
    }
    __syncthreads();
    float out = red[0];
    __syncthreads();
    return out;
}

// ---------------- K0: split W into tf32 hi/lo (runs once per weight matrix) ----------
__global__ __launch_bounds__(256) void split_w_kernel(const float* __restrict__ W,
                                                      unsigned* __restrict__ hi,
                                                      unsigned* __restrict__ lo) {
    size_t i = ((size_t)blockIdx.x * 256 + threadIdx.x) * 4;
    float4 v = *(const float4*)(W + i);
    uint4 h, l;
    h.x = f2tf32(v.x); l.x = f2tf32(v.x - __uint_as_float(h.x));
    h.y = f2tf32(v.y); l.y = f2tf32(v.y - __uint_as_float(h.y));
    h.z = f2tf32(v.z); l.z = f2tf32(v.z - __uint_as_float(h.z));
    h.w = f2tf32(v.w); l.w = f2tf32(v.w - __uint_as_float(h.w));
    *(uint4*)(hi + i) = h;
    *(uint4*)(lo + i) = l;
}

// ---------------- K1/K6: LayerNorm stats only (mu, rstd per row) ----------------
__global__ __launch_bounds__(256) void ln_stats_kernel(const float* __restrict__ x) {
    __shared__ float red[8];
    const size_t base = (size_t)blockIdx.x * D_DIM;
    const int t = threadIdx.x;
    float v0 = x[base + t];
    float v1 = x[base + t + 256];
    float v2 = x[base + t + 512];
    float s1 = block_sum256(v0 + v1 + v2, red);
    float s2 = block_sum256(v0 * v0 + v1 * v1 + v2 * v2, red);
    const float inv_d = 1.0f / (float)D_DIM;
    float mu = s1 * inv_d;
    float var = fmaxf(s2 * inv_d - mu * mu, 0.0f);
    if (t == 0) {
        g_lnstats[blockIdx.x * 2 + 0] = mu;
        g_lnstats[blockIdx.x * 2 + 1] = rsqrtf(var + LN_EPS);
    }
}

// ---------------- K2/K7: fused LN + QKV GEMM (3xTF32, double-buffered pipeline) ------
#define QKV_AS_STRIDE 136
#define QKV_AS_TILE   (16 * QKV_AS_STRIDE)        // 2176
#define QKV_BS_STRIDE 20
#define QKV_BS_TILE   (128 * QKV_BS_STRIDE)       // 2560
#define QKV_SMEM_FLOATS (2 * QKV_AS_TILE + 4 * QKV_BS_TILE + 128 + 128 + 768 + 768) // 16384
__global__ __launch_bounds__(256, 2) void qkv_gemm_tc(const float* __restrict__ x,
                                                      const unsigned* __restrict__ Whi,
                                                      const unsigned* __restrict__ Wlo,
                                                      const float* __restrict__ bias,
                                                      const float* __restrict__ gamma,
                                                      const float* __restrict__ beta) {
    extern __shared__ float sm[];
    float* As = sm;                                   // 2 tiles
    unsigned* Bsh = (unsigned*)(sm + 2 * QKV_AS_TILE);
    unsigned* Bsl = Bsh + 2 * QKV_BS_TILE;
    float* mu_s = (float*)(Bsl + 2 * QKV_BS_TILE);
    float* rs_s = mu_s + 128;
    float* gs = rs_s + 128;
    float* bs = gs + 768;

    const int tid = threadIdx.x;
    const int wid = tid >> 5, lane = tid & 31;
    const int warp_m = (wid >> 1) * 32;      // 0,32,64,96
    const int warp_n = (wid & 1) * 64;       // 0,64
    const int r = lane >> 2, c = lane & 3;
    const int m0 = blockIdx.y * 128;
    const int n0 = blockIdx.x * 128;

    const int rr0 = tid >> 2;                 // 0..63
    const int rr1 = rr0 + 64;                 // 64..127
    const int cc = (tid & 3) << 2;            // 0,4,8,12

    if (tid < 128) {
        mu_s[tid] = g_lnstats[(m0 + tid) * 2 + 0];
        rs_s[tid] = g_lnstats[(m0 + tid) * 2 + 1];
    }
    for (int i = tid; i < 768; i += 256) {
        gs[i] = gamma[i];
        bs[i] = beta[i];
    }
    __syncthreads();

    float acc[2][8][4];
#pragma unroll
    for (int t = 0; t < 2; t++)
#pragma unroll
        for (int u = 0; u < 8; u++)
#pragma unroll
            for (int v = 0; v < 4; v++) acc[t][u][v] = 0.0f;

    // ---- prologue: stage tile 0 ----
    {
#pragma unroll
        for (int q = 0; q < 2; q++) {
            int rr = q ? rr1 : rr0;
            float4 va = *(const float4*)(x + (size_t)(m0 + rr) * D_DIM + cc);
            float mu = mu_s[rr], rs = rs_s[rr];
            As[(cc + 0) * QKV_AS_STRIDE + rr] = (va.x - mu) * rs * gs[cc + 0] + bs[cc + 0];
            As[(cc + 1) * QKV_AS_STRIDE + rr] = (va.y - mu) * rs * gs[cc + 1] + bs[cc + 1];
            As[(cc + 2) * QKV_AS_STRIDE + rr] = (va.z - mu) * rs * gs[cc + 2] + bs[cc + 2];
            As[(cc + 3) * QKV_AS_STRIDE + rr] = (va.w - mu) * rs * gs[cc + 3] + bs[cc + 3];
        }
#pragma unroll
        for (int q = 0; q < 2; q++) {
            int rr = q ? rr1 : rr0;
            size_t woff = (size_t)(n0 + rr) * D_DIM + cc;
            cp_async16(&Bsh[rr * QKV_BS_STRIDE + cc], Whi + woff);
            cp_async16(&Bsl[rr * QKV_BS_STRIDE + cc], Wlo + woff);
        }
        CP_COMMIT();
    }

    for (int kt = 0; kt < 48; kt++) {
        const int b = kt & 1;
        CP_WAIT0();
        __syncthreads();

        const bool has_next = (kt < 47);
        const int k0n = (kt + 1) * 16;
        float4 va_n[2];
        if (has_next) {
#pragma unroll
            for (int q = 0; q < 2; q++) {
                int rr = q ? rr1 : rr0;
                va_n[q] = *(const float4*)(x + (size_t)(m0 + rr) * D_DIM + k0n + cc);
                size_t woff = (size_t)(n0 + rr) * D_DIM + k0n + cc;
                cp_async16(&Bsh[(b ^ 1) * QKV_BS_TILE + rr * QKV_BS_STRIDE + cc], Whi + woff);
                cp_async16(&Bsl[(b ^ 1) * QKV_BS_TILE + rr * QKV_BS_STRIDE + cc], Wlo + woff);
            }
            CP_COMMIT();
        }

        const float* Ab = As + b * QKV_AS_TILE;
        const unsigned* Bhb = Bsh + b * QKV_BS_TILE;
        const unsigned* Blb = Bsl + b * QKV_BS_TILE;
#pragma unroll
        for (int k8 = 0; k8 < 16; k8 += 8) {
            unsigned Ahi[2][4], Alo[2][4];
#pragma unroll
            for (int t = 0; t < 2; t++) {
                int m = warp_m + t * 16 + r;
                float x0 = Ab[(k8 + c) * QKV_AS_STRIDE + m];
                float x1 = Ab[(k8 + c) * QKV_AS_STRIDE + m + 8];
                float x2 = Ab[(k8 + c + 4) * QKV_AS_STRIDE + m];
                float x3 = Ab[(k8 + c + 4) * QKV_AS_STRIDE + m + 8];
                Ahi[t][0] = f2tf32(x0); Alo[t][0] = f2tf32(x0 - __uint_as_float(Ahi[t][0]));
                Ahi[t][1] = f2tf32(x1); Alo[t][1] = f2tf32(x1 - __uint_as_float(Ahi[t][1]));
                Ahi[t][2] = f2tf32(x2); Alo[t][2] = f2tf32(x2 - __uint_as_float(Ahi[t][2]));
                Ahi[t][3] = f2tf32(x3); Alo[t][3] = f2tf32(x3 - __uint_as_float(Ahi[t][3]));
            }
#pragma unroll
            for (int u = 0; u < 8; u++) {
                int n = warp_n + u * 8 + r;
                unsigned Bh[2], Bl[2];
                Bh[0] = Bhb[n * QKV_BS_STRIDE + k8 + c];
                Bh[1] = Bhb[n * QKV_BS_STRIDE + k8 + 4 + c];
                Bl[0] = Blb[n * QKV_BS_STRIDE + k8 + c];
                Bl[1] = Blb[n * QKV_BS_STRIDE + k8 + 4 + c];
#pragma unroll
                for (int t = 0; t < 2; t++) {
                    mma_tf32(acc[t][u], Ahi[t], Bh);
                    mma_tf32(acc[t][u], Ahi[t], Bl);
                    mma_tf32(acc[t][u], Alo[t], Bh);
                }
            }
        }

        if (has_next) {
            float* An = As + (b ^ 1) * QKV_AS_TILE;
#pragma unroll
            for (int q = 0; q < 2; q++) {
                int rr = q ? rr1 : rr0;
                float mu = mu_s[rr], rs = rs_s[rr];
                float4 va = va_n[q];
                An[(cc + 0) * QKV_AS_STRIDE + rr] = (va.x - mu) * rs * gs[k0n + cc + 0] + bs[k0n + cc + 0];
                An[(cc + 1) * QKV_AS_STRIDE + rr] = (va.y - mu) * rs * gs[k0n + cc + 1] + bs[k0n + cc + 1];
                An[(cc + 2) * QKV_AS_STRIDE + rr] = (va.z - mu) * rs * gs[k0n + cc + 2] + bs[k0n + cc + 2];
                An[(cc + 3) * QKV_AS_STRIDE + rr] = (va.w - mu) * rs * gs[k0n + cc + 3] + bs[k0n + cc + 3];
            }
        }
    }

#pragma unroll
    for (int t = 0; t < 2; t++) {
        int row0 = m0 + warp_m + t * 16 + r;
#pragma unroll
        for (int u = 0; u < 8; u++) {
            int col = n0 + warp_n + u * 8 + c * 2;
            float2 bz = *(const float2*)(bias + col);
            float2 v0, v1;
            v0.x = acc[t][u][0] + bz.x; v0.y = acc[t][u][1] + bz.y;
            v1.x = acc[t][u][2] + bz.x; v1.y = acc[t][u][3] + bz.y;
            *(float2*)(g_proj + (size_t)row0 * TD_DIM + col) = v0;
            *(float2*)(g_proj + (size_t)(row0 + 8) * TD_DIM + col) = v1;
        }
    }
}

// ---------------- K3a: zero scores + row mask sums ----------------
__global__ __launch_bounds__(256) void scores_zero_kernel(const float* __restrict__ mask) {
    size_t idx = (size_t)blockIdx.x * 1024 + threadIdx.x * 4;
    if (idx < (size_t)H_DIM * L_DIM * L_DIM) {
        float4 z = {0.f, 0.f, 0.f, 0.f};
        *(float4*)(g_scores + idx) = z;
    }
    int t = blockIdx.x * 256 + threadIdx.x;   // [0, H*L)
    if (t < H_DIM * L_DIM) {
        int h = t / L_DIM, j = t % L_DIM;
        float s = 0.0f;
        for (int e = 0; e < E_DIM; e++) s += mask[((size_t)h * E_DIM + e) * L_DIM + j];
        g_rowmask[t] = s;
    }
}

// ---------------- K3b: row scores (tensor cores, 3xTF32) -------------------------
__global__ __launch_bounds__(256, 2) void row_scores_tc() {
    __shared__ unsigned As_h[16][136], As_l[16][136];
    __shared__ unsigned Bs_h[16][136], Bs_l[16][136];
    const int tid = threadIdx.x;
    const int wid = tid >> 5, lane = tid & 31;
    const int warp_m = (wid >> 1) * 32;
    const int warp_n = (wid & 1) * 64;
    const int r = lane >> 2, c = lane & 3;
    const int it = (blockIdx.x >> 1) * 128;
    const int jt = (blockIdx.x & 1) * 128;
    const int h = blockIdx.y;
    const int e0 = blockIdx.z * 16;

    float acc[2][8][4];
#pragma unroll
    for (int t = 0; t < 2; t++)
#pragma unroll
        for (int u = 0; u < 8; u++)
#pragma unroll
            for (int v = 0; v < 4; v++) acc[t][u][v] = 0.0f;

    for (int e = e0; e < e0 + 16; e++) {
        const float* qbase = g_proj + (size_t)(e * L_DIM) * TD_DIM + h * DH_DIM;
        const float* kbase = qbase + D_DIM;
        for (int k0 = 0; k0 < DH_DIM; k0 += 16) {
#pragma unroll
            for (int q = 0; q < 2; q++) {
                int id = q * 256 + tid;
                int rr = id >> 2;
                int c4 = (id & 3) << 2;
                float4 va = *(const float4*)(qbase + (size_t)(it + rr) * TD_DIM + k0 + c4);
                unsigned hh;
                hh = f2tf32(va.x); As_h[c4 + 0][rr] = hh; As_l[c4 + 0][rr] = f2tf32(va.x - __uint_as_float(hh));
                hh = f2tf32(va.y); As_h[c4 + 1][rr] = hh; As_l[c4 + 1][rr] = f2tf32(va.y - __uint_as_float(hh));
                hh = f2tf32(va.z); As_h[c4 + 2][rr] = hh; As_l[c4 + 2][rr] = f2tf32(va.z - __uint_as_float(hh));
                hh = f2tf32(va.w); As_h[c4 + 3][rr] = hh; As_l[c4 + 3][rr] = f2tf32(va.w - __uint_as_float(hh));
                float4 vb = *(const float4*)(kbase + (size_t)(jt + rr) * TD_DIM + k0 + c4);
                hh = f2tf32(vb.x); Bs_h[c4 + 0][rr] = hh; Bs_l[c4 + 0][rr] = f2tf32(vb.x - __uint_as_float(hh));
                hh = f2tf32(vb.y); Bs_h[c4 + 1][rr] = hh; Bs_l[c4 + 1][rr] = f2tf32(vb.y - __uint_as_float(hh));
                hh = f2tf32(vb.z); Bs_h[c4 + 2][rr] = hh; Bs_l[c4 + 2][rr] = f2tf32(vb.z - __uint_as_float(hh));
                hh = f2tf32(vb.w); Bs_h[c4 + 3][rr] = hh; Bs_l[c4 + 3][rr] = f2tf32(vb.w - __uint_as_float(hh));
            }
            __syncthreads();
#pragma unroll
            for (int k8 = 0; k8 < 16; k8 += 8) {
                unsigned Ah[2][4], Al[2][4];
#pragma unroll
                for (int t = 0; t < 2; t++) {
                    int m = warp_m + t * 16 + r;
                    Ah[t][0] = As_h[k8 + c][m];     Al[t][0] = As_l[k8 + c][m];
                    Ah[t][1] = As_h[k8 + c][m + 8]; Al[t][1] = As_l[k8 + c][m + 8];
                    Ah[t][2] = As_h[k8 + c + 4][m];     Al[t][2] = As_l[k8 + c + 4][m];
                    Ah[t][3] = As_h[k8 + c + 4][m + 8]; Al[t][3] = As_l[k8 + c + 4][m + 8];
                }
#pragma unroll
                for (int u = 0; u < 8; u++) {
                    int n = warp_n + u * 8 + r;
                    unsigned Bh[2], Bl[2];
                    Bh[0] = Bs_h[k8 + c][n];     Bl[0] = Bs_l[k8 + c][n];
                    Bh[1] = Bs_h[k8 + 4 + c][n]; Bl[1] = Bs_l[k8 + 4 + c][n];
#pragma unroll
                    for (int t = 0; t < 2; t++) {
                        mma_tf32(acc[t][u], Ah[t], Bh);
                        mma_tf32(acc[t][u], Ah[t], Bl);
                        mma_tf32(acc[t][u], Al[t], Bh);
                    }
                }
            }
            __syncthreads();
        }
    }

#pragma unroll
    for (int t = 0; t < 2; t++) {
        int row = it + warp_m + t * 16 + r;
#pragma unroll
        for (int u = 0; u < 8; u++) {
            int col = jt + warp_n + u * 8 + c * 2;
            float* p0 = &g_scores[((size_t)h * L_DIM + row) * L_DIM + col];
            atomicAdd(p0, acc[t][u][0]);
            atomicAdd(p0 + 1, acc[t][u][1]);
            float* p1 = &g_scores[((size_t)h * L_DIM + row + 8) * L_DIM + col];
            atomicAdd(p1, acc[t][u][2]);
            atomicAdd(p1 + 1, acc[t][u][3]);
        }
    }
}

// ---------------- K4: softmax over j (adds row mask on the fly) ----------------
__global__ __launch_bounds__(256) void row_softmax_kernel() {
    __shared__ float red[8];
    int h = blockIdx.x / L_DIM;
    float* row = g_scores + (size_t)blockIdx.x * L_DIM;
    float v = row[threadIdx.x] + g_rowmask[h * L_DIM + threadIdx.x];
    float m = block_max256(v, red);
    float p = __expf(v - m);
    float s = block_sum256(p, red);
    row[threadIdx.x] = p / s;
}

// ---------------- K5: row AV + residual (tensor cores, 3xTF32) -------------------
// out[e, it+i, h, c] = x[...] + sum_j P[h, it+i, j] * V[e, j, h, c]
// M=128 (i), N=64 (c), K=256 (j). 8 warps: 4(m) x 2(n), warp tile 32x32.
// grid: (2 [i-tile], 12 [h], 128 [e])
__global__ __launch_bounds__(256) void row_av_tc(const float* __restrict__ x,
                                                 float* __restrict__ out) {
    __shared__ float As[16][136];   // P^T: [j][i]  (fragment reads conflict-free: 136%32=8)
    __shared__ float Bs[16][68];    // V:   [j][c]  (68%32=4 -> conflict-free)
    const int tid = threadIdx.x;
    const int wid = tid >> 5, lane = tid & 31;
    const int warp_m = (wid >> 1) * 32;       // 0,32,64,96
    const int warp_n = (wid & 1) * 32;        // 0,32
    const int r = lane >> 2, c = lane & 3;
    const int it = blockIdx.x * 128;
    const int h = blockIdx.y;
    const int e = blockIdx.z;

    const float* pbase = g_scores + (size_t)h * L_DIM * L_DIM;
    const float* vbase = g_proj + (size_t)(e * L_DIM) * TD_DIM + 2 * D_DIM + h * DH_DIM;

    // staging coords
    const int rr0 = tid >> 2, rr1 = rr0 + 64;     // P rows (i)
    const int cc = (tid & 3) << 2;                // P cols (j within tile)
    const int vj = tid >> 4;                      // V row (j within tile), 0..15
    const int vc = (tid & 15) << 2;               // V col (c), 0..60

    float acc[2][4][4];
#pragma unroll
    for (int t = 0; t < 2; t++)
#pragma unroll
        for (int u = 0; u < 4; u++)
#pragma unroll
            for (int v = 0; v < 4; v++) acc[t][u][v] = 0.0f;

    for (int kt = 0; kt < 16; kt++) {
        const int j0 = kt * 16;
        // stage P^T tile: As[j][i]
#pragma unroll
        for (int q = 0; q < 2; q++) {
            int rr = q ? rr1 : rr0;
            float4 p = *(const float4*)(pbase + (size_t)(it + rr) * L_DIM + j0 + cc);
            As[cc + 0][rr] = p.x; As[cc + 1][rr] = p.y;
            As[cc + 2][rr] = p.z; As[cc + 3][rr] = p.w;
        }
        // stage V tile: Bs[j][c]
        {
            float4 v = *(const float4*)(vbase + (size_t)(j0 + vj) * TD_DIM + vc);
            *(float4*)&Bs[vj][vc] = v;
        }
        __syncthreads();
#pragma unroll
        for (int k8 = 0; k8 < 16; k8 += 8) {
            unsigned Ahi[2][4], Alo[2][4];
#pragma unroll
            for (int t = 0; t < 2; t++) {
                int m = warp_m + t * 16 + r;
                float x0 = As[k8 + c][m];
                float x1 = As[k8 + c][m + 8];
                float x2 = As[k8 + c + 4][m];
                float x3 = As[k8 + c + 4][m + 8];
                Ahi[t][0] = f2tf32(x0); Alo[t][0] = f2tf32(x0 - __uint_as_float(Ahi[t][0]));
                Ahi[t][1] = f2tf32(x1); Alo[t][1] = f2tf32(x1 - __uint_as_float(Ahi[t][1]));
                Ahi[t][2] = f2tf32(x2); Alo[t][2] = f2tf32(x2 - __uint_as_float(Ahi[t][2]));
                Ahi[t][3] = f2tf32(x3); Alo[t][3] = f2tf32(x3 - __uint_as_float(Ahi[t][3]));
            }
#pragma unroll
            for (int u = 0; u < 4; u++) {
                int n = warp_n + u * 8 + r;
                float y0 = Bs[k8 + c][n];
                float y1 = Bs[k8 + 4 + c][n];
                unsigned Bh[2], Bl[2];
                Bh[0] = f2tf32(y0); Bl[0] = f2tf32(y0 - __uint_as_float(Bh[0]));
                Bh[1] = f2tf32(y1); Bl[1] = f2tf32(y1 - __uint_as_float(Bh[1]));
#pragma unroll
                for (int t = 0; t < 2; t++) {
                    mma_tf32(acc[t][u], Ahi[t], Bh);
                    mma_tf32(acc[t][u], Ahi[t], Bl);
                    mma_tf32(acc[t][u], Alo[t], Bh);
                }
            }
        }
        __syncthreads();
    }

    // epilogue: residual add + store
#pragma unroll
    for (int t = 0; t < 2; t++) {
        int row = it + warp_m + t * 16 + r;
#pragma unroll
        for (int u = 0; u < 4; u++) {
            int col = warp_n + u * 8 + c * 2;
            size_t off0 = ((size_t)(e * L_DIM + row)) * D_DIM + h * DH_DIM + col;
            size_t off1 = ((size_t)(e * L_DIM + row + 8)) * D_DIM + h * DH_DIM + col;
            float2 x0 = *(const float2*)(x + off0);
            float2 x1 = *(const float2*)(x + off1);
            float2 v0, v1;
            v0.x = x0.x + acc[t][u][0]; v0.y = x0.y + acc[t][u][1];
            v1.x = x1.x + acc[t][u][2]; v1.y = x1.y + acc[t][u][3];
            *(float2*)(out + off0) = v0;
            *(float2*)(out + off1) = v1;
        }
    }
}

// ---------------- K8: fused column attention, one block per (h,l) ----------------
#define COL_SMEM_FLOATS (64 * 128 + 128 * 64 + 128 * 128 + 256)
__global__ __launch_bounds__(256) void col_attn_kernel(const float* __restrict__ mask,
                                                       float* __restrict__ out) {
    extern __shared__ float sm[];
    float* Ks = sm;                    // [c][j]  64 x 128
    float* Vs = Ks + 64 * 128;         // [j][c]  128 x 64
    float* Ss = Vs + 128 * 64;         // [j][i]  128 x 128 (first 64x128 doubles as Qs)
    float* red2 = Ss + 128 * 128;      // 256 floats
    float* Qs = Ss;                    // [c][i]  64 x 128 alias
    const int tid = threadIdx.x;
    const int tx = tid & 15, ty = tid >> 4;
    const int l = blockIdx.x;
    const int h = blockIdx.y;

    const float* qbase = g_proj + (size_t)l * TD_DIM + h * DH_DIM;   // + i*L*TD
    const float* kbase = qbase + D_DIM;
    const float* vbase = qbase + 2 * D_DIM;

#pragma unroll
    for (int q = 0; q < 8; q++) {
        int id = q * 256 + tid;                 // 2048 float4 per tensor
        int r = id & 127;
        int c4 = ((id >> 7) & 15) << 2;
        float4 va = *(const float4*)(qbase + (size_t)r * L_DIM * TD_DIM + c4);
        Qs[(c4 + 0) * 128 + r] = va.x; Qs[(c4 + 1) * 128 + r] = va.y;
        Qs[(c4 + 2) * 128 + r] = va.z; Qs[(c4 + 3) * 128 + r] = va.w;
        float4 vb = *(const float4*)(kbase + (size_t)r * L_DIM * TD_DIM + c4);
        Ks[(c4 + 0) * 128 + r] = vb.x; Ks[(c4 + 1) * 128 + r] = vb.y;
        Ks[(c4 + 2) * 128 + r] = vb.z; Ks[(c4 + 3) * 128 + r] = vb.w;
        int rJ = id >> 4;
        int c42 = (id & 15) << 2;
        *(float4*)&Vs[rJ * 64 + c42] = *(const float4*)(vbase + (size_t)rJ * L_DIM * TD_DIM + c42);
    }
    __syncthreads();

    float accS[8][8];   // [jj][ii]
    {
#pragma unroll
        for (int j = 0; j < 8; j++)
#pragma unroll
            for (int i = 0; i < 8; i++) accS[j][i] = 0.0f;
#pragma unroll
        for (int c = 0; c < 64; c++) {
            float ai[8], bj[8];
            *(float4*)&ai[0] = *(const float4*)&Qs[c * 128 + tx * 8];
            *(float4*)&ai[4] = *(const float4*)&Qs[c * 128 + tx * 8 + 4];
            *(float4*)&bj[0] = *(const float4*)&Ks[c * 128 + ty * 8];
            *(float4*)&bj[4] = *(const float4*)&Ks[c * 128 + ty * 8 + 4];
#pragma unroll
            for (int j = 0; j < 8; j++)
#pragma unroll
                for (int i = 0; i < 8; i++) accS[j][i] = fmaf(ai[i], bj[j], accS[j][i]);
        }
    }
    __syncthreads();   // all Qs reads done before Ss overwrites the alias region
    {
#pragma unroll
        for (int jj = 0; jj < 8; jj++) {
            int j = ty * 8 + jj;
            float mk = mask[((size_t)h * E_DIM + j) * L_DIM + l];
#pragma unroll
            for (int i0 = 0; i0 < 8; i0 += 4) {
                float4 v;
                v.x = accS[jj][i0 + 0] + mk;
                v.y = accS[jj][i0 + 1] + mk;
                v.z = accS[jj][i0 + 2] + mk;
                v.w = accS[jj][i0 + 3] + mk;
                *(float4*)&Ss[j * 128 + tx * 8 + i0] = v;
            }
        }
    }
    __syncthreads();

    {
        const int i = tid & 127;
        const int half = tid >> 7;
        const int j0 = half * 64;
        float m = -3.4e38f;
#pragma unroll 8
        for (int j = 0; j < 64; j++) m = fmaxf(m, Ss[(j0 + j) * 128 + i]);
        red2[tid] = m;
        __syncthreads();
        m = fmaxf(red2[i], red2[i + 128]);
        float s = 0.0f;
#pragma unroll 8
        for (int j = 0; j < 64; j++) {
            float p = __expf(Ss[(j0 + j) * 128 + i] - m);
            Ss[(j0 + j) * 128 + i] = p;
            s += p;
        }
        __syncthreads();
        red2[tid] = s;
        __syncthreads();
        float inv = 1.0f / (red2[i] + red2[i + 128]);
#pragma unroll 8
        for (int j = 0; j < 64; j++) Ss[(j0 + j) * 128 + i] *= inv;
    }
    __syncthreads();

    {
        float accO[8][4];
#pragma unroll
        for (int i = 0; i < 8; i++)
#pragma unroll
            for (int c = 0; c < 4; c++) accO[i][c] = 0.0f;
#pragma unroll 4
        for (int jj = 0; jj < 128; jj++) {
            float ai[8], bc[4];
            *(float4*)&ai[0] = *(const float4*)&Ss[jj * 128 + ty * 8];
            *(float4*)&ai[4] = *(const float4*)&Ss[jj * 128 + ty * 8 + 4];
            *(float4*)&bc[0] = *(const float4*)&Vs[jj * 64 + tx * 4];
#pragma unroll
            for (int i = 0; i < 8; i++)
#pragma unroll
                for (int c = 0; c < 4; c++) accO[i][c] = fmaf(ai[i], bc[c], accO[i][c]);
        }
#pragma unroll
        for (int ii = 0; ii < 8; ii++) {
            int i = ty * 8 + ii;
            size_t off = ((size_t)i * L_DIM + l) * D_DIM + h * DH_DIM + tx * 4;
            float4 cur = *(const float4*)(out + off);
            cur.x += accO[ii][0];
            cur.y += accO[ii][1];
            cur.z += accO[ii][2];
            cur.w += accO[ii][3];
            *(float4*)(out + off) = cur;
        }
    }
}

// ---------------- launcher ----------------
extern "C" void kernel_launch(void* const* d_in, const int* in_sizes, int n_in,
                              void* d_out, int out_size) {
    const float* x     = (const float*)d_in[0];
    const float* mask  = (const float*)d_in[1];
    const float* w_row = (const float*)d_in[2];
    const float* b_row = (const float*)d_in[3];
    const float* w_col = (const float*)d_in[4];
    const float* b_col = (const float*)d_in[5];
    const float* g1    = (const float*)d_in[6];
    const float* be1   = (const float*)d_in[7];
    const float* g2    = (const float*)d_in[8];
    const float* be2   = (const float*)d_in[9];
    float* out = (float*)d_out;

    unsigned *wr_hi, *wr_lo, *wc_hi, *wc_lo;
    cudaGetSymbolAddress((void**)&wr_hi, g_wr_hi);
    cudaGetSymbolAddress((void**)&wr_lo, g_wr_lo);
    cudaGetSymbolAddress((void**)&wc_hi, g_wc_hi);
    cudaGetSymbolAddress((void**)&wc_lo, g_wc_lo);

    const int col_smem = COL_SMEM_FLOATS * (int)sizeof(float);   // ~100 KB
    const int qkv_smem = QKV_SMEM_FLOATS * (int)sizeof(float);   // 64 KB
    cudaFuncSetAttribute(col_attn_kernel, cudaFuncAttributeMaxDynamicSharedMemorySize, col_smem);
    cudaFuncSetAttribute(qkv_gemm_tc, cudaFuncAttributeMaxDynamicSharedMemorySize, qkv_smem);

    const int wsplit_blocks = (TD_DIM * D_DIM) / (256 * 4);   // 1728

    // ---- row attention stage ----
    split_w_kernel<<<wsplit_blocks, 256>>>(w_row, wr_hi, wr_lo);
    split_w_kernel<<<wsplit_blocks, 256>>>(w_col, wc_hi, wc_lo);
    ln_stats_kernel<<<N_ROWS, 256>>>(x);
    qkv_gemm_tc<<<dim3(TD_DIM / 128, N_ROWS / 128), 256, qkv_smem>>>(x, wr_hi, wr_lo, b_row, g1, be1);
    scores_zero_kernel<<<(H_DIM * L_DIM * L_DIM) / 1024, 256>>>(mask);
    row_scores_tc<<<dim3(4, H_DIM, 8), 256>>>();
    row_softmax_kernel<<<H_DIM * L_DIM, 256>>>();
    row_av_tc<<<dim3(2, H_DIM, E_DIM), 256>>>(x, out);   // out = x + row_out

    // ---- column attention stage ----
    ln_stats_kernel<<<N_ROWS, 256>>>(out);
    qkv_gemm_tc<<<dim3(TD_DIM / 128, N_ROWS / 128), 256, qkv_smem>>>(out, wc_hi, wc_lo, b_col, g2, be2);
    col_attn_kernel<<<dim3(L_DIM, H_DIM), 256, col_smem>>>(mask, out);  // out += col_out
}

// round 11
// speedup vs baseline: 1.2498x; 1.0055x over previous
#include <cuda_runtime.h>
#include <cuda_bf16.h>
#include <cstdint>

// ---------------- problem constants ----------------
#define E_DIM 128
#define L_DIM 256
#define H_DIM 12
#define DH_DIM 64
#define D_DIM 768          // H*DH
#define TD_DIM 2304        // 3*D
#define N_ROWS 32768       // E*L
#define LN_EPS 1e-5f

// ---------------- scratch (__device__ globals; no cudaMalloc allowed) ----------------
__device__ float g_proj[(size_t)N_ROWS * TD_DIM];          // QKV projection     (~302 MB)
__device__ float g_scores[(size_t)H_DIM * L_DIM * L_DIM];  // row scores/maps    (~3 MB)
__device__ float g_rowmask[H_DIM * L_DIM];                 // sum_e mask[h,e,j]
__device__ unsigned g_wr_hi[(size_t)TD_DIM * D_DIM];       // w_row tf32 hi (7 MB)
__device__ unsigned g_wr_lo[(size_t)TD_DIM * D_DIM];       // w_row tf32 lo
__device__ unsigned g_wc_hi[(size_t)TD_DIM * D_DIM];       // w_col tf32 hi
__device__ unsigned g_wc_lo[(size_t)TD_DIM * D_DIM];       // w_col tf32 lo
__device__ unsigned g_xh[(size_t)N_ROWS * D_DIM];          // LN(x) tf32 hi (100 MB)
__device__ unsigned g_xl[(size_t)N_ROWS * D_DIM];          // LN(x) tf32 lo (100 MB)

// ---------------- tf32 / async helpers ----------------
__device__ __forceinline__ unsigned f2tf32(float x) {
    unsigned u;
    asm("cvt.rna.tf32.f32 %0, %1;" : "=r"(u) : "f"(x));
    return u;
}
__device__ __forceinline__ void mma_tf32(float* d, const unsigned* a, const unsigned* b) {
    asm volatile(
        "mma.sync.aligned.m16n8k8.row.col.f32.tf32.tf32.f32 "
        "{%0,%1,%2,%3}, {%4,%5,%6,%7}, {%8,%9}, {%0,%1,%2,%3};\n"
        : "+f"(d[0]), "+f"(d[1]), "+f"(d[2]), "+f"(d[3])
        : "r"(a[0]), "r"(a[1]), "r"(a[2]), "r"(a[3]), "r"(b[0]), "r"(b[1]));
}
__device__ __forceinline__ void cp_async16(void* smem, const void* gmem) {
    unsigned saddr = (unsigned)__cvta_generic_to_shared(smem);
    asm volatile("cp.async.cg.shared.global [%0], [%1], 16;\n" :: "r"(saddr), "l"(gmem));
}
#define CP_COMMIT() asm volatile("cp.async.commit_group;\n" ::: "memory")
#define CP_WAIT0()  asm volatile("cp.async.wait_group 0;\n" ::: "memory")

// ---------------- reductions ----------------
__device__ __forceinline__ float warp_sum(float v) {
#pragma unroll
    for (int o = 16; o; o >>= 1) v += __shfl_xor_sync(0xffffffffu, v, o);
    return v;
}
__device__ __forceinline__ float warp_max(float v) {
#pragma unroll
    for (int o = 16; o; o >>= 1) v = fmaxf(v, __shfl_xor_sync(0xffffffffu, v, o));
    return v;
}
__device__ __forceinline__ float block_sum256(float v, float* red) {
    int lane = threadIdx.x & 31, w = threadIdx.x >> 5;
    v = warp_sum(v);
    if (lane == 0) red[w] = v;
    __syncthreads();
    if (threadIdx.x < 8) {
        float r = red[threadIdx.x];
        r += __shfl_xor_sync(0xffu, r, 4);
        r += __shfl_xor_sync(0xffu, r, 2);
        r += __shfl_xor_sync(0xffu, r, 1);
        if (threadIdx.x == 0) red[0] = r;
    }
    __syncthreads();
    float out = red[0];
    __syncthreads();
    return out;
}
__device__ __forceinline__ float block_max256(float v, float* red) {
    int lane = threadIdx.x & 31, w = threadIdx.x >> 5;
    v = warp_max(v);
    if (lane == 0) red[w] = v;
    __syncthreads();
    if (threadIdx.x < 8) {
        float r = red[threadIdx.x];
        r = fmaxf(r, __shfl_xor_sync(0xffu, r, 4));
        r = fmaxf(r, __shfl_xor_sync(0xffu, r, 2));
        r = fmaxf(r, __shfl_xor_sync(0xffu, r, 1));
        if (threadIdx.x == 0) red[0] = r;
    }
    __syncthreads();
    float out = red[0];
    __syncthreads();
    return out;
}

// ---------------- K0: split W into tf32 hi/lo (runs once per weight matrix) ----------
__global__ __launch_bounds__(256) void split_w_kernel(const float* __restrict__ W,
                                                      unsigned* __restrict__ hi,
                                                      unsigned* __restrict__ lo) {
    size_t i = ((size_t)blockIdx.x * 256 + threadIdx.x) * 4;
    float4 v = *(const float4*)(W + i);
    uint4 h, l;
    h.x = f2tf32(v.x); l.x = f2tf32(v.x - __uint_as_float(h.x));
    h.y = f2tf32(v.y); l.y = f2tf32(v.y - __uint_as_float(h.y));
    h.z = f2tf32(v.z); l.z = f2tf32(v.z - __uint_as_float(h.z));
    h.w = f2tf32(v.w); l.w = f2tf32(v.w - __uint_as_float(h.w));
    *(uint4*)(hi + i) = h;
    *(uint4*)(lo + i) = l;
}

// ---------------- K1/K6: LayerNorm + tf32 hi/lo split (one pass) ----------------
// Computes row stats, applies LN+gamma+beta, writes tf32-split result to g_xh/g_xl.
__global__ __launch_bounds__(256) void ln_split_kernel(const float* __restrict__ x,
                                                       const float* __restrict__ gamma,
                                                       const float* __restrict__ beta) {
    __shared__ float red[8];
    const size_t base = (size_t)blockIdx.x * D_DIM;
    const int t = threadIdx.x;
    float v0 = x[base + t];
    float v1 = x[base + t + 256];
    float v2 = x[base + t + 512];
    float s1 = block_sum256(v0 + v1 + v2, red);
    float s2 = block_sum256(v0 * v0 + v1 * v1 + v2 * v2, red);
    const float inv_d = 1.0f / (float)D_DIM;
    float mu = s1 * inv_d;
    float var = fmaxf(s2 * inv_d - mu * mu, 0.0f);
    float rs = rsqrtf(var + LN_EPS);
#pragma unroll
    for (int q = 0; q < 3; q++) {
        int idx = t + q * 256;
        float v = (q == 0) ? v0 : (q == 1) ? v1 : v2;
        float f = (v - mu) * rs * gamma[idx] + beta[idx];
        unsigned h = f2tf32(f);
        g_xh[base + idx] = h;
        g_xl[base + idx] = f2tf32(f - __uint_as_float(h));
    }
}

// ---------------- K2/K7: QKV GEMM (3xTF32, both operands pre-split, pure LDS+MMA) ----
// C[N,2304] = LN(x)[N,768] * W[2304,768]^T + bias
// Block tile 128x128, warp tile 32x64 (8 warps). All four operand planes staged
// via cp.async into [row][20]-stride tiles (conflict-free fragment LDS).
#define QKV_T_STRIDE 20
#define QKV_T_TILE   (128 * QKV_T_STRIDE)         // 2560 u32 per tile
#define QKV_SMEM_BYTES (8 * QKV_T_TILE * 4)       // 4 planes x 2 buffers = 81920 B
__global__ __launch_bounds__(256, 2) void qkv_gemm_tc(const unsigned* __restrict__ Ahi_g,
                                                      const unsigned* __restrict__ Alo_g,
                                                      const unsigned* __restrict__ Whi,
                                                      const unsigned* __restrict__ Wlo,
                                                      const float* __restrict__ bias) {
    extern __shared__ unsigned usm[];
    unsigned* Ash = usm;                          // [2][128][20]
    unsigned* Asl = Ash + 2 * QKV_T_TILE;
    unsigned* Bsh = Asl + 2 * QKV_T_TILE;
    unsigned* Bsl = Bsh + 2 * QKV_T_TILE;

    const int tid = threadIdx.x;
    const int wid = tid >> 5, lane = tid & 31;
    const int warp_m = (wid >> 1) * 32;      // 0,32,64,96
    const int warp_n = (wid & 1) * 64;       // 0,64
    const int r = lane >> 2, c = lane & 3;
    const int m0 = blockIdx.y * 128;
    const int n0 = blockIdx.x * 128;

    const int rr0 = tid >> 2;                 // 0..63
    const int rr1 = rr0 + 64;                 // 64..127
    const int cc = (tid & 3) << 2;            // 0,4,8,12

    float acc[2][8][4];
#pragma unroll
    for (int t = 0; t < 2; t++)
#pragma unroll
        for (int u = 0; u < 8; u++)
#pragma unroll
            for (int v = 0; v < 4; v++) acc[t][u][v] = 0.0f;

    // ---- prologue: stage tile 0 ----
#pragma unroll
    for (int q = 0; q < 2; q++) {
        int rr = q ? rr1 : rr0;
        size_t aoff = (size_t)(m0 + rr) * D_DIM + cc;
        size_t woff = (size_t)(n0 + rr) * D_DIM + cc;
        cp_async16(&Ash[rr * QKV_T_STRIDE + cc], Ahi_g + aoff);
        cp_async16(&Asl[rr * QKV_T_STRIDE + cc], Alo_g + aoff);
        cp_async16(&Bsh[rr * QKV_T_STRIDE + cc], Whi + woff);
        cp_async16(&Bsl[rr * QKV_T_STRIDE + cc], Wlo + woff);
    }
    CP_COMMIT();

    for (int kt = 0; kt < 48; kt++) {
        const int b = kt & 1;
        CP_WAIT0();
        __syncthreads();

        if (kt < 47) {
            const int k0n = (kt + 1) * 16;
            const int bo = (b ^ 1) * QKV_T_TILE;
#pragma unroll
            for (int q = 0; q < 2; q++) {
                int rr = q ? rr1 : rr0;
                size_t aoff = (size_t)(m0 + rr) * D_DIM + k0n + cc;
                size_t woff = (size_t)(n0 + rr) * D_DIM + k0n + cc;
                cp_async16(&Ash[bo + rr * QKV_T_STRIDE + cc], Ahi_g + aoff);
                cp_async16(&Asl[bo + rr * QKV_T_STRIDE + cc], Alo_g + aoff);
                cp_async16(&Bsh[bo + rr * QKV_T_STRIDE + cc], Whi + woff);
                cp_async16(&Bsl[bo + rr * QKV_T_STRIDE + cc], Wlo + woff);
            }
            CP_COMMIT();
        }

        const unsigned* Ahb = Ash + b * QKV_T_TILE;
        const unsigned* Alb = Asl + b * QKV_T_TILE;
        const unsigned* Bhb = Bsh + b * QKV_T_TILE;
        const unsigned* Blb = Bsl + b * QKV_T_TILE;
#pragma unroll
        for (int k8 = 0; k8 < 16; k8 += 8) {
            unsigned Ahi[2][4], Alo[2][4];
#pragma unroll
            for (int t = 0; t < 2; t++) {
                int m = warp_m + t * 16 + r;
                Ahi[t][0] = Ahb[m * QKV_T_STRIDE + k8 + c];
                Ahi[t][1] = Ahb[(m + 8) * QKV_T_STRIDE + k8 + c];
                Ahi[t][2] = Ahb[m * QKV_T_STRIDE + k8 + c + 4];
                Ahi[t][3] = Ahb[(m + 8) * QKV_T_STRIDE + k8 + c + 4];
                Alo[t][0] = Alb[m * QKV_T_STRIDE + k8 + c];
                Alo[t][1] = Alb[(m + 8) * QKV_T_STRIDE + k8 + c];
                Alo[t][2] = Alb[m * QKV_T_STRIDE + k8 + c + 4];
                Alo[t][3] = Alb[(m + 8) * QKV_T_STRIDE + k8 + c + 4];
            }
#pragma unroll
            for (int u = 0; u < 8; u++) {
                int n = warp_n + u * 8 + r;
                unsigned Bh[2], Bl[2];
                Bh[0] = Bhb[n * QKV_T_STRIDE + k8 + c];
                Bh[1] = Bhb[n * QKV_T_STRIDE + k8 + 4 + c];
                Bl[0] = Blb[n * QKV_T_STRIDE + k8 + c];
                Bl[1] = Blb[n * QKV_T_STRIDE + k8 + 4 + c];
#pragma unroll
                for (int t = 0; t < 2; t++) {
                    mma_tf32(acc[t][u], Ahi[t], Bh);
                    mma_tf32(acc[t][u], Ahi[t], Bl);
                    mma_tf32(acc[t][u], Alo[t], Bh);
                }
            }
        }
    }

    // ---- epilogue: bias add + store ----
#pragma unroll
    for (int t = 0; t < 2; t++) {
        int row0 = m0 + warp_m + t * 16 + r;
#pragma unroll
        for (int u = 0; u < 8; u++) {
            int col = n0 + warp_n + u * 8 + c * 2;
            float2 bz = *(const float2*)(bias + col);
            float2 v0, v1;
            v0.x = acc[t][u][0] + bz.x; v0.y = acc[t][u][1] + bz.y;
            v1.x = acc[t][u][2] + bz.x; v1.y = acc[t][u][3] + bz.y;
            *(float2*)(g_proj + (size_t)row0 * TD_DIM + col) = v0;
            *(float2*)(g_proj + (size_t)(row0 + 8) * TD_DIM + col) = v1;
        }
    }
}

// ---------------- K3a: zero scores + row mask sums ----------------
__global__ __launch_bounds__(256) void scores_zero_kernel(const float* __restrict__ mask) {
    size_t idx = (size_t)blockIdx.x * 1024 + threadIdx.x * 4;
    if (idx < (size_t)H_DIM * L_DIM * L_DIM) {
        float4 z = {0.f, 0.f, 0.f, 0.f};
        *(float4*)(g_scores + idx) = z;
    }
    int t = blockIdx.x * 256 + threadIdx.x;   // [0, H*L)
    if (t < H_DIM * L_DIM) {
        int h = t / L_DIM, j = t % L_DIM;
        float s = 0.0f;
        for (int e = 0; e < E_DIM; e++) s += mask[((size_t)h * E_DIM + e) * L_DIM + j];
        g_rowmask[t] = s;
    }
}

// ---------------- K3b: row scores (tensor cores, 3xTF32) -------------------------
__global__ __launch_bounds__(256, 2) void row_scores_tc() {
    __shared__ unsigned As_h[16][136], As_l[16][136];
    __shared__ unsigned Bs_h[16][136], Bs_l[16][136];
    const int tid = threadIdx.x;
    const int wid = tid >> 5, lane = tid & 31;
    const int warp_m = (wid >> 1) * 32;
    const int warp_n = (wid & 1) * 64;
    const int r = lane >> 2, c = lane & 3;
    const int it = (blockIdx.x >> 1) * 128;
    const int jt = (blockIdx.x & 1) * 128;
    const int h = blockIdx.y;
    const int e0 = blockIdx.z * 16;

    float acc[2][8][4];
#pragma unroll
    for (int t = 0; t < 2; t++)
#pragma unroll
        for (int u = 0; u < 8; u++)
#pragma unroll
            for (int v = 0; v < 4; v++) acc[t][u][v] = 0.0f;

    for (int e = e0; e < e0 + 16; e++) {
        const float* qbase = g_proj + (size_t)(e * L_DIM) * TD_DIM + h * DH_DIM;
        const float* kbase = qbase + D_DIM;
        for (int k0 = 0; k0 < DH_DIM; k0 += 16) {
#pragma unroll
            for (int q = 0; q < 2; q++) {
                int id = q * 256 + tid;
                int rr = id >> 2;
                int c4 = (id & 3) << 2;
                float4 va = *(const float4*)(qbase + (size_t)(it + rr) * TD_DIM + k0 + c4);
                unsigned hh;
                hh = f2tf32(va.x); As_h[c4 + 0][rr] = hh; As_l[c4 + 0][rr] = f2tf32(va.x - __uint_as_float(hh));
                hh = f2tf32(va.y); As_h[c4 + 1][rr] = hh; As_l[c4 + 1][rr] = f2tf32(va.y - __uint_as_float(hh));
                hh = f2tf32(va.z); As_h[c4 + 2][rr] = hh; As_l[c4 + 2][rr] = f2tf32(va.z - __uint_as_float(hh));
                hh = f2tf32(va.w); As_h[c4 + 3][rr] = hh; As_l[c4 + 3][rr] = f2tf32(va.w - __uint_as_float(hh));
                float4 vb = *(const float4*)(kbase + (size_t)(jt + rr) * TD_DIM + k0 + c4);
                hh = f2tf32(vb.x); Bs_h[c4 + 0][rr] = hh; Bs_l[c4 + 0][rr] = f2tf32(vb.x - __uint_as_float(hh));
                hh = f2tf32(vb.y); Bs_h[c4 + 1][rr] = hh; Bs_l[c4 + 1][rr] = f2tf32(vb.y - __uint_as_float(hh));
                hh = f2tf32(vb.z); Bs_h[c4 + 2][rr] = hh; Bs_l[c4 + 2][rr] = f2tf32(vb.z - __uint_as_float(hh));
                hh = f2tf32(vb.w); Bs_h[c4 + 3][rr] = hh; Bs_l[c4 + 3][rr] = f2tf32(vb.w - __uint_as_float(hh));
            }
            __syncthreads();
#pragma unroll
            for (int k8 = 0; k8 < 16; k8 += 8) {
                unsigned Ah[2][4], Al[2][4];
#pragma unroll
                for (int t = 0; t < 2; t++) {
                    int m = warp_m + t * 16 + r;
                    Ah[t][0] = As_h[k8 + c][m];     Al[t][0] = As_l[k8 + c][m];
                    Ah[t][1] = As_h[k8 + c][m + 8]; Al[t][1] = As_l[k8 + c][m + 8];
                    Ah[t][2] = As_h[k8 + c + 4][m];     Al[t][2] = As_l[k8 + c + 4][m];
                    Ah[t][3] = As_h[k8 + c + 4][m + 8]; Al[t][3] = As_l[k8 + c + 4][m + 8];
                }
#pragma unroll
                for (int u = 0; u < 8; u++) {
                    int n = warp_n + u * 8 + r;
                    unsigned Bh[2], Bl[2];
                    Bh[0] = Bs_h[k8 + c][n];     Bl[0] = Bs_l[k8 + c][n];
                    Bh[1] = Bs_h[k8 + 4 + c][n]; Bl[1] = Bs_l[k8 + 4 + c][n];
#pragma unroll
                    for (int t = 0; t < 2; t++) {
                        mma_tf32(acc[t][u], Ah[t], Bh);
                        mma_tf32(acc[t][u], Ah[t], Bl);
                        mma_tf32(acc[t][u], Al[t], Bh);
                    }
                }
            }
            __syncthreads();
        }
    }

#pragma unroll
    for (int t = 0; t < 2; t++) {
        int row = it + warp_m + t * 16 + r;
#pragma unroll
        for (int u = 0; u < 8; u++) {
            int col = jt + warp_n + u * 8 + c * 2;
            float* p0 = &g_scores[((size_t)h * L_DIM + row) * L_DIM + col];
            atomicAdd(p0, acc[t][u][0]);
            atomicAdd(p0 + 1, acc[t][u][1]);
            float* p1 = &g_scores[((size_t)h * L_DIM + row + 8) * L_DIM + col];
            atomicAdd(p1, acc[t][u][2]);
            atomicAdd(p1 + 1, acc[t][u][3]);
        }
    }
}

// ---------------- K4: softmax over j (adds row mask on the fly) ----------------
__global__ __launch_bounds__(256) void row_softmax_kernel() {
    __shared__ float red[8];
    int h = blockIdx.x / L_DIM;
    float* row = g_scores + (size_t)blockIdx.x * L_DIM;
    float v = row[threadIdx.x] + g_rowmask[h * L_DIM + threadIdx.x];
    float m = block_max256(v, red);
    float p = __expf(v - m);
    float s = block_sum256(p, red);
    row[threadIdx.x] = p / s;
}

// ---------------- K5: row AV + residual (tensor cores, 3xTF32) -------------------
__global__ __launch_bounds__(256) void row_av_tc(const float* __restrict__ x,
                                                 float* __restrict__ out) {
    __shared__ float As[16][136];   // P^T: [j][i]
    __shared__ float Bs[16][68];    // V:   [j][c]
    const int tid = threadIdx.x;
    const int wid = tid >> 5, lane = tid & 31;
    const int warp_m = (wid >> 1) * 32;       // 0,32,64,96
    const int warp_n = (wid & 1) * 32;        // 0,32
    const int r = lane >> 2, c = lane & 3;
    const int it = blockIdx.x * 128;
    const int h = blockIdx.y;
    const int e = blockIdx.z;

    const float* pbase = g_scores + (size_t)h * L_DIM * L_DIM;
    const float* vbase = g_proj + (size_t)(e * L_DIM) * TD_DIM + 2 * D_DIM + h * DH_DIM;

    const int rr0 = tid >> 2, rr1 = rr0 + 64;
    const int cc = (tid & 3) << 2;
    const int vj = tid >> 4;
    const int vc = (tid & 15) << 2;

    float acc[2][4][4];
#pragma unroll
    for (int t = 0; t < 2; t++)
#pragma unroll
        for (int u = 0; u < 4; u++)
#pragma unroll
            for (int v = 0; v < 4; v++) acc[t][u][v] = 0.0f;

    for (int kt = 0; kt < 16; kt++) {
        const int j0 = kt * 16;
#pragma unroll
        for (int q = 0; q < 2; q++) {
            int rr = q ? rr1 : rr0;
            float4 p = *(const float4*)(pbase + (size_t)(it + rr) * L_DIM + j0 + cc);
            As[cc + 0][rr] = p.x; As[cc + 1][rr] = p.y;
            As[cc + 2][rr] = p.z; As[cc + 3][rr] = p.w;
        }
        {
            float4 v = *(const float4*)(vbase + (size_t)(j0 + vj) * TD_DIM + vc);
            *(float4*)&Bs[vj][vc] = v;
        }
        __syncthreads();
#pragma unroll
        for (int k8 = 0; k8 < 16; k8 += 8) {
            unsigned Ahi[2][4], Alo[2][4];
#pragma unroll
            for (int t = 0; t < 2; t++) {
                int m = warp_m + t * 16 + r;
                float x0 = As[k8 + c][m];
                float x1 = As[k8 + c][m + 8];
                float x2 = As[k8 + c + 4][m];
                float x3 = As[k8 + c + 4][m + 8];
                Ahi[t][0] = f2tf32(x0); Alo[t][0] = f2tf32(x0 - __uint_as_float(Ahi[t][0]));
                Ahi[t][1] = f2tf32(x1); Alo[t][1] = f2tf32(x1 - __uint_as_float(Ahi[t][1]));
                Ahi[t][2] = f2tf32(x2); Alo[t][2] = f2tf32(x2 - __uint_as_float(Ahi[t][2]));
                Ahi[t][3] = f2tf32(x3); Alo[t][3] = f2tf32(x3 - __uint_as_float(Ahi[t][3]));
            }
#pragma unroll
            for (int u = 0; u < 4; u++) {
                int n = warp_n + u * 8 + r;
                float y0 = Bs[k8 + c][n];
                float y1 = Bs[k8 + 4 + c][n];
                unsigned Bh[2], Bl[2];
                Bh[0] = f2tf32(y0); Bl[0] = f2tf32(y0 - __uint_as_float(Bh[0]));
                Bh[1] = f2tf32(y1); Bl[1] = f2tf32(y1 - __uint_as_float(Bh[1]));
#pragma unroll
                for (int t = 0; t < 2; t++) {
                    mma_tf32(acc[t][u], Ahi[t], Bh);
                    mma_tf32(acc[t][u], Ahi[t], Bl);
                    mma_tf32(acc[t][u], Alo[t], Bh);
                }
            }
        }
        __syncthreads();
    }

#pragma unroll
    for (int t = 0; t < 2; t++) {
        int row = it + warp_m + t * 16 + r;
#pragma unroll
        for (int u = 0; u < 4; u++) {
            int col = warp_n + u * 8 + c * 2;
            size_t off0 = ((size_t)(e * L_DIM + row)) * D_DIM + h * DH_DIM + col;
            size_t off1 = ((size_t)(e * L_DIM + row + 8)) * D_DIM + h * DH_DIM + col;
            float2 x0 = *(const float2*)(x + off0);
            float2 x1 = *(const float2*)(x + off1);
            float2 v0, v1;
            v0.x = x0.x + acc[t][u][0]; v0.y = x0.y + acc[t][u][1];
            v1.x = x1.x + acc[t][u][2]; v1.y = x1.y + acc[t][u][3];
            *(float2*)(out + off0) = v0;
            *(float2*)(out + off1) = v1;
        }
    }
}

// ---------------- K8: fused column attention, one block per (h,l) ----------------
#define COL_SMEM_FLOATS (64 * 128 + 128 * 64 + 128 * 128 + 256)
__global__ __launch_bounds__(256) void col_attn_kernel(const float* __restrict__ mask,
                                                       float* __restrict__ out) {
    extern __shared__ float sm[];
    float* Ks = sm;                    // [c][j]  64 x 128
    float* Vs = Ks + 64 * 128;         // [j][c]  128 x 64
    float* Ss = Vs + 128 * 64;         // [j][i]  128 x 128 (first 64x128 doubles as Qs)
    float* red2 = Ss + 128 * 128;      // 256 floats
    float* Qs = Ss;                    // [c][i]  64 x 128 alias
    const int tid = threadIdx.x;
    const int tx = tid & 15, ty = tid >> 4;
    const int l = blockIdx.x;
    const int h = blockIdx.y;

    const float* qbase = g_proj + (size_t)l * TD_DIM + h * DH_DIM;   // + i*L*TD
    const float* kbase = qbase + D_DIM;
    const float* vbase = qbase + 2 * D_DIM;

#pragma unroll
    for (int q = 0; q < 8; q++) {
        int id = q * 256 + tid;                 // 2048 float4 per tensor
        int r = id & 127;
        int c4 = ((id >> 7) & 15) << 2;
        float4 va = *(const float4*)(qbase + (size_t)r * L_DIM * TD_DIM + c4);
        Qs[(c4 + 0) * 128 + r] = va.x; Qs[(c4 + 1) * 128 + r] = va.y;
        Qs[(c4 + 2) * 128 + r] = va.z; Qs[(c4 + 3) * 128 + r] = va.w;
        float4 vb = *(const float4*)(kbase + (size_t)r * L_DIM * TD_DIM + c4);
        Ks[(c4 + 0) * 128 + r] = vb.x; Ks[(c4 + 1) * 128 + r] = vb.y;
        Ks[(c4 + 2) * 128 + r] = vb.z; Ks[(c4 + 3) * 128 + r] = vb.w;
        int rJ = id >> 4;
        int c42 = (id & 15) << 2;
        *(float4*)&Vs[rJ * 64 + c42] = *(const float4*)(vbase + (size_t)rJ * L_DIM * TD_DIM + c42);
    }
    __syncthreads();

    float accS[8][8];   // [jj][ii]
    {
#pragma unroll
        for (int j = 0; j < 8; j++)
#pragma unroll
            for (int i = 0; i < 8; i++) accS[j][i] = 0.0f;
#pragma unroll
        for (int c = 0; c < 64; c++) {
            float ai[8], bj[8];
            *(float4*)&ai[0] = *(const float4*)&Qs[c * 128 + tx * 8];
            *(float4*)&ai[4] = *(const float4*)&Qs[c * 128 + tx * 8 + 4];
            *(float4*)&bj[0] = *(const float4*)&Ks[c * 128 + ty * 8];
            *(float4*)&bj[4] = *(const float4*)&Ks[c * 128 + ty * 8 + 4];
#pragma unroll
            for (int j = 0; j < 8; j++)
#pragma unroll
                for (int i = 0; i < 8; i++) accS[j][i] = fmaf(ai[i], bj[j], accS[j][i]);
        }
    }
    __syncthreads();   // all Qs reads done before Ss overwrites the alias region
    {
#pragma unroll
        for (int jj = 0; jj < 8; jj++) {
            int j = ty * 8 + jj;
            float mk = mask[((size_t)h * E_DIM + j) * L_DIM + l];
#pragma unroll
            for (int i0 = 0; i0 < 8; i0 += 4) {
                float4 v;
                v.x = accS[jj][i0 + 0] + mk;
                v.y = accS[jj][i0 + 1] + mk;
                v.z = accS[jj][i0 + 2] + mk;
                v.w = accS[jj][i0 + 3] + mk;
                *(float4*)&Ss[j * 128 + tx * 8 + i0] = v;
            }
        }
    }
    __syncthreads();

    {
        const int i = tid & 127;
        const int half = tid >> 7;
        const int j0 = half * 64;
        float m = -3.4e38f;
#pragma unroll 8
        for (int j = 0; j < 64; j++) m = fmaxf(m, Ss[(j0 + j) * 128 + i]);
        red2[tid] = m;
        __syncthreads();
        m = fmaxf(red2[i], red2[i + 128]);
        float s = 0.0f;
#pragma unroll 8
        for (int j = 0; j < 64; j++) {
            float p = __expf(Ss[(j0 + j) * 128 + i] - m);
            Ss[(j0 + j) * 128 + i] = p;
            s += p;
        }
        __syncthreads();
        red2[tid] = s;
        __syncthreads();
        float inv = 1.0f / (red2[i] + red2[i + 128]);
#pragma unroll 8
        for (int j = 0; j < 64; j++) Ss[(j0 + j) * 128 + i] *= inv;
    }
    __syncthreads();

    {
        float accO[8][4];
#pragma unroll
        for (int i = 0; i < 8; i++)
#pragma unroll
            for (int c = 0; c < 4; c++) accO[i][c] = 0.0f;
#pragma unroll 4
        for (int jj = 0; jj < 128; jj++) {
            float ai[8], bc[4];
            *(float4*)&ai[0] = *(const float4*)&Ss[jj * 128 + ty * 8];
            *(float4*)&ai[4] = *(const float4*)&Ss[jj * 128 + ty * 8 + 4];
            *(float4*)&bc[0] = *(const float4*)&Vs[jj * 64 + tx * 4];
#pragma unroll
            for (int i = 0; i < 8; i++)
#pragma unroll
                for (int c = 0; c < 4; c++) accO[i][c] = fmaf(ai[i], bc[c], accO[i][c]);
        }
#pragma unroll
        for (int ii = 0; ii < 8; ii++) {
            int i = ty * 8 + ii;
            size_t off = ((size_t)i * L_DIM + l) * D_DIM + h * DH_DIM + tx * 4;
            float4 cur = *(const float4*)(out + off);
            cur.x += accO[ii][0];
            cur.y += accO[ii][1];
            cur.z += accO[ii][2];
            cur.w += accO[ii][3];
            *(float4*)(out + off) = cur;
        }
    }
}

// ---------------- launcher ----------------
extern "C" void kernel_launch(void* const* d_in, const int* in_sizes, int n_in,
                              void* d_out, int out_size) {
    const float* x     = (const float*)d_in[0];
    const float* mask  = (const float*)d_in[1];
    const float* w_row = (const float*)d_in[2];
    const float* b_row = (const float*)d_in[3];
    const float* w_col = (const float*)d_in[4];
    const float* b_col = (const float*)d_in[5];
    const float* g1    = (const float*)d_in[6];
    const float* be1   = (const float*)d_in[7];
    const float* g2    = (const float*)d_in[8];
    const float* be2   = (const float*)d_in[9];
    float* out = (float*)d_out;

    unsigned *wr_hi, *wr_lo, *wc_hi, *wc_lo, *xh, *xl;
    cudaGetSymbolAddress((void**)&wr_hi, g_wr_hi);
    cudaGetSymbolAddress((void**)&wr_lo, g_wr_lo);
    cudaGetSymbolAddress((void**)&wc_hi, g_wc_hi);
    cudaGetSymbolAddress((void**)&wc_lo, g_wc_lo);
    cudaGetSymbolAddress((void**)&xh, g_xh);
    cudaGetSymbolAddress((void**)&xl, g_xl);

    const int col_smem = COL_SMEM_FLOATS * (int)sizeof(float);   // ~100 KB
    cudaFuncSetAttribute(col_attn_kernel, cudaFuncAttributeMaxDynamicSharedMemorySize, col_smem);
    cudaFuncSetAttribute(qkv_gemm_tc, cudaFuncAttributeMaxDynamicSharedMemorySize, QKV_SMEM_BYTES);

    const int wsplit_blocks = (TD_DIM * D_DIM) / (256 * 4);   // 1728

    // ---- row attention stage ----
    split_w_kernel<<<wsplit_blocks, 256>>>(w_row, wr_hi, wr_lo);
    split_w_kernel<<<wsplit_blocks, 256>>>(w_col, wc_hi, wc_lo);
    ln_split_kernel<<<N_ROWS, 256>>>(x, g1, be1);
    qkv_gemm_tc<<<dim3(TD_DIM / 128, N_ROWS / 128), 256, QKV_SMEM_BYTES>>>(xh, xl, wr_hi, wr_lo, b_row);
    scores_zero_kernel<<<(H_DIM * L_DIM * L_DIM) / 1024, 256>>>(mask);
    row_scores_tc<<<dim3(4, H_DIM, 8), 256>>>();
    row_softmax_kernel<<<H_DIM * L_DIM, 256>>>();
    row_av_tc<<<dim3(2, H_DIM, E_DIM), 256>>>(x, out);   // out = x + row_out

    // ---- column attention stage ----
    ln_split_kernel<<<N_ROWS, 256>>>(out, g2, be2);
    qkv_gemm_tc<<<dim3(TD_DIM / 128, N_ROWS / 128), 256, QKV_SMEM_BYTES>>>(xh, xl, wc_hi, wc_lo, b_col);
    col_attn_kernel<<<dim3(L_DIM, H_DIM), 256, col_smem>>>(mask, out);  // out += col_out
}

// round 12
// speedup vs baseline: 1.2648x; 1.0120x over previous
#include <cuda_runtime.h>
#include <cuda_bf16.h>
#include <cstdint>

// ---------------- problem constants ----------------
#define E_DIM 128
#define L_DIM 256
#define H_DIM 12
#define DH_DIM 64
#define D_DIM 768          // H*DH
#define TD_DIM 2304        // 3*D
#define N_ROWS 32768       // E*L
#define LN_EPS 1e-5f

// ---------------- scratch (__device__ globals; no cudaMalloc allowed) ----------------
__device__ float g_proj[(size_t)N_ROWS * TD_DIM];          // QKV projection     (~302 MB)
__device__ float g_scores[(size_t)H_DIM * L_DIM * L_DIM];  // row scores/maps    (~3 MB)
__device__ float g_rowmask[H_DIM * L_DIM];                 // sum_e mask[h,e,j]
__device__ unsigned g_wr_hi[(size_t)TD_DIM * D_DIM];       // w_row tf32 hi (7 MB)
__device__ unsigned g_wr_lo[(size_t)TD_DIM * D_DIM];       // w_row tf32 lo
__device__ unsigned g_wc_hi[(size_t)TD_DIM * D_DIM];       // w_col tf32 hi
__device__ unsigned g_wc_lo[(size_t)TD_DIM * D_DIM];       // w_col tf32 lo
__device__ unsigned g_xh[(size_t)N_ROWS * D_DIM];          // LN(x) tf32 hi (100 MB)
__device__ unsigned g_xl[(size_t)N_ROWS * D_DIM];          // LN(x) tf32 lo (100 MB)

// ---------------- tf32 / async helpers ----------------
__device__ __forceinline__ unsigned f2tf32(float x) {
    unsigned u;
    asm("cvt.rna.tf32.f32 %0, %1;" : "=r"(u) : "f"(x));
    return u;
}
__device__ __forceinline__ void mma_tf32(float* d, const unsigned* a, const unsigned* b) {
    asm volatile(
        "mma.sync.aligned.m16n8k8.row.col.f32.tf32.tf32.f32 "
        "{%0,%1,%2,%3}, {%4,%5,%6,%7}, {%8,%9}, {%0,%1,%2,%3};\n"
        : "+f"(d[0]), "+f"(d[1]), "+f"(d[2]), "+f"(d[3])
        : "r"(a[0]), "r"(a[1]), "r"(a[2]), "r"(a[3]), "r"(b[0]), "r"(b[1]));
}
__device__ __forceinline__ void cp_async16(void* smem, const void* gmem) {
    unsigned saddr = (unsigned)__cvta_generic_to_shared(smem);
    asm volatile("cp.async.cg.shared.global [%0], [%1], 16;\n" :: "r"(saddr), "l"(gmem));
}
#define CP_COMMIT() asm volatile("cp.async.commit_group;\n" ::: "memory")
#define CP_WAIT0()  asm volatile("cp.async.wait_group 0;\n" ::: "memory")

// split a float to tf32 hi/lo
__device__ __forceinline__ void split3(float x, unsigned& h, unsigned& l) {
    h = f2tf32(x);
    l = f2tf32(x - __uint_as_float(h));
}

// ---------------- reductions ----------------
__device__ __forceinline__ float warp_sum(float v) {
#pragma unroll
    for (int o = 16; o; o >>= 1) v += __shfl_xor_sync(0xffffffffu, v, o);
    return v;
}
__device__ __forceinline__ float warp_max(float v) {
#pragma unroll
    for (int o = 16; o; o >>= 1) v = fmaxf(v, __shfl_xor_sync(0xffffffffu, v, o));
    return v;
}
__device__ __forceinline__ float block_sum256(float v, float* red) {
    int lane = threadIdx.x & 31, w = threadIdx.x >> 5;
    v = warp_sum(v);
    if (lane == 0) red[w] = v;
    __syncthreads();
    if (threadIdx.x < 8) {
        float r = red[threadIdx.x];
        r += __shfl_xor_sync(0xffu, r, 4);
        r += __shfl_xor_sync(0xffu, r, 2);
        r += __shfl_xor_sync(0xffu, r, 1);
        if (threadIdx.x == 0) red[0] = r;
    }
    __syncthreads();
    float out = red[0];
    __syncthreads();
    return out;
}
__device__ __forceinline__ float block_max256(float v, float* red) {
    int lane = threadIdx.x & 31, w = threadIdx.x >> 5;
    v = warp_max(v);
    if (lane == 0) red[w] = v;
    __syncthreads();
    if (threadIdx.x < 8) {
        float r = red[threadIdx.x];
        r = fmaxf(r, __shfl_xor_sync(0xffu, r, 4));
        r = fmaxf(r, __shfl_xor_sync(0xffu, r, 2));
        r = fmaxf(r, __shfl_xor_sync(0xffu, r, 1));
        if (threadIdx.x == 0) red[0] = r;
    }
    __syncthreads();
    float out = red[0];
    __syncthreads();
    return out;
}

// ---------------- K0: split W into tf32 hi/lo ----------------
__global__ __launch_bounds__(256) void split_w_kernel(const float* __restrict__ W,
                                                      unsigned* __restrict__ hi,
                                                      unsigned* __restrict__ lo) {
    size_t i = ((size_t)blockIdx.x * 256 + threadIdx.x) * 4;
    float4 v = *(const float4*)(W + i);
    uint4 h, l;
    h.x = f2tf32(v.x); l.x = f2tf32(v.x - __uint_as_float(h.x));
    h.y = f2tf32(v.y); l.y = f2tf32(v.y - __uint_as_float(h.y));
    h.z = f2tf32(v.z); l.z = f2tf32(v.z - __uint_as_float(h.z));
    h.w = f2tf32(v.w); l.w = f2tf32(v.w - __uint_as_float(h.w));
    *(uint4*)(hi + i) = h;
    *(uint4*)(lo + i) = l;
}

// ---------------- K1/K6: LayerNorm + tf32 hi/lo split (one pass) ----------------
__global__ __launch_bounds__(256) void ln_split_kernel(const float* __restrict__ x,
                                                       const float* __restrict__ gamma,
                                                       const float* __restrict__ beta) {
    __shared__ float red[8];
    const size_t base = (size_t)blockIdx.x * D_DIM;
    const int t = threadIdx.x;
    float v0 = x[base + t];
    float v1 = x[base + t + 256];
    float v2 = x[base + t + 512];
    float s1 = block_sum256(v0 + v1 + v2, red);
    float s2 = block_sum256(v0 * v0 + v1 * v1 + v2 * v2, red);
    const float inv_d = 1.0f / (float)D_DIM;
    float mu = s1 * inv_d;
    float var = fmaxf(s2 * inv_d - mu * mu, 0.0f);
    float rs = rsqrtf(var + LN_EPS);
#pragma unroll
    for (int q = 0; q < 3; q++) {
        int idx = t + q * 256;
        float v = (q == 0) ? v0 : (q == 1) ? v1 : v2;
        float f = (v - mu) * rs * gamma[idx] + beta[idx];
        unsigned h = f2tf32(f);
        g_xh[base + idx] = h;
        g_xl[base + idx] = f2tf32(f - __uint_as_float(h));
    }
}

// ---------------- K2/K7: QKV GEMM (3xTF32, pre-split operands, pipelined) ----------
#define QKV_T_STRIDE 20
#define QKV_T_TILE   (128 * QKV_T_STRIDE)         // 2560 u32 per tile
#define QKV_SMEM_BYTES (8 * QKV_T_TILE * 4)       // 81920 B
__global__ __launch_bounds__(256, 2) void qkv_gemm_tc(const unsigned* __restrict__ Ahi_g,
                                                      const unsigned* __restrict__ Alo_g,
                                                      const unsigned* __restrict__ Whi,
                                                      const unsigned* __restrict__ Wlo,
                                                      const float* __restrict__ bias) {
    extern __shared__ unsigned usm[];
    unsigned* Ash = usm;                          // [2][128][20]
    unsigned* Asl = Ash + 2 * QKV_T_TILE;
    unsigned* Bsh = Asl + 2 * QKV_T_TILE;
    unsigned* Bsl = Bsh + 2 * QKV_T_TILE;

    const int tid = threadIdx.x;
    const int wid = tid >> 5, lane = tid & 31;
    const int warp_m = (wid >> 1) * 32;
    const int warp_n = (wid & 1) * 64;
    const int r = lane >> 2, c = lane & 3;
    const int m0 = blockIdx.y * 128;
    const int n0 = blockIdx.x * 128;

    const int rr0 = tid >> 2;
    const int rr1 = rr0 + 64;
    const int cc = (tid & 3) << 2;

    float acc[2][8][4];
#pragma unroll
    for (int t = 0; t < 2; t++)
#pragma unroll
        for (int u = 0; u < 8; u++)
#pragma unroll
            for (int v = 0; v < 4; v++) acc[t][u][v] = 0.0f;

#pragma unroll
    for (int q = 0; q < 2; q++) {
        int rr = q ? rr1 : rr0;
        size_t aoff = (size_t)(m0 + rr) * D_DIM + cc;
        size_t woff = (size_t)(n0 + rr) * D_DIM + cc;
        cp_async16(&Ash[rr * QKV_T_STRIDE + cc], Ahi_g + aoff);
        cp_async16(&Asl[rr * QKV_T_STRIDE + cc], Alo_g + aoff);
        cp_async16(&Bsh[rr * QKV_T_STRIDE + cc], Whi + woff);
        cp_async16(&Bsl[rr * QKV_T_STRIDE + cc], Wlo + woff);
    }
    CP_COMMIT();

    for (int kt = 0; kt < 48; kt++) {
        const int b = kt & 1;
        CP_WAIT0();
        __syncthreads();

        if (kt < 47) {
            const int k0n = (kt + 1) * 16;
            const int bo = (b ^ 1) * QKV_T_TILE;
#pragma unroll
            for (int q = 0; q < 2; q++) {
                int rr = q ? rr1 : rr0;
                size_t aoff = (size_t)(m0 + rr) * D_DIM + k0n + cc;
                size_t woff = (size_t)(n0 + rr) * D_DIM + k0n + cc;
                cp_async16(&Ash[bo + rr * QKV_T_STRIDE + cc], Ahi_g + aoff);
                cp_async16(&Asl[bo + rr * QKV_T_STRIDE + cc], Alo_g + aoff);
                cp_async16(&Bsh[bo + rr * QKV_T_STRIDE + cc], Whi + woff);
                cp_async16(&Bsl[bo + rr * QKV_T_STRIDE + cc], Wlo + woff);
            }
            CP_COMMIT();
        }

        const unsigned* Ahb = Ash + b * QKV_T_TILE;
        const unsigned* Alb = Asl + b * QKV_T_TILE;
        const unsigned* Bhb = Bsh + b * QKV_T_TILE;
        const unsigned* Blb = Bsl + b * QKV_T_TILE;
#pragma unroll
        for (int k8 = 0; k8 < 16; k8 += 8) {
            unsigned Ahi[2][4], Alo[2][4];
#pragma unroll
            for (int t = 0; t < 2; t++) {
                int m = warp_m + t * 16 + r;
                Ahi[t][0] = Ahb[m * QKV_T_STRIDE + k8 + c];
                Ahi[t][1] = Ahb[(m + 8) * QKV_T_STRIDE + k8 + c];
                Ahi[t][2] = Ahb[m * QKV_T_STRIDE + k8 + c + 4];
                Ahi[t][3] = Ahb[(m + 8) * QKV_T_STRIDE + k8 + c + 4];
                Alo[t][0] = Alb[m * QKV_T_STRIDE + k8 + c];
                Alo[t][1] = Alb[(m + 8) * QKV_T_STRIDE + k8 + c];
                Alo[t][2] = Alb[m * QKV_T_STRIDE + k8 + c + 4];
                Alo[t][3] = Alb[(m + 8) * QKV_T_STRIDE + k8 + c + 4];
            }
#pragma unroll
            for (int u = 0; u < 8; u++) {
                int n = warp_n + u * 8 + r;
                unsigned Bh[2], Bl[2];
                Bh[0] = Bhb[n * QKV_T_STRIDE + k8 + c];
                Bh[1] = Bhb[n * QKV_T_STRIDE + k8 + 4 + c];
                Bl[0] = Blb[n * QKV_T_STRIDE + k8 + c];
                Bl[1] = Blb[n * QKV_T_STRIDE + k8 + 4 + c];
#pragma unroll
                for (int t = 0; t < 2; t++) {
                    mma_tf32(acc[t][u], Ahi[t], Bh);
                    mma_tf32(acc[t][u], Ahi[t], Bl);
                    mma_tf32(acc[t][u], Alo[t], Bh);
                }
            }
        }
    }

#pragma unroll
    for (int t = 0; t < 2; t++) {
        int row0 = m0 + warp_m + t * 16 + r;
#pragma unroll
        for (int u = 0; u < 8; u++) {
            int col = n0 + warp_n + u * 8 + c * 2;
            float2 bz = *(const float2*)(bias + col);
            float2 v0, v1;
            v0.x = acc[t][u][0] + bz.x; v0.y = acc[t][u][1] + bz.y;
            v1.x = acc[t][u][2] + bz.x; v1.y = acc[t][u][3] + bz.y;
            *(float2*)(g_proj + (size_t)row0 * TD_DIM + col) = v0;
            *(float2*)(g_proj + (size_t)(row0 + 8) * TD_DIM + col) = v1;
        }
    }
}

// ---------------- K3a: zero scores + row mask sums ----------------
__global__ __launch_bounds__(256) void scores_zero_kernel(const float* __restrict__ mask) {
    size_t idx = (size_t)blockIdx.x * 1024 + threadIdx.x * 4;
    if (idx < (size_t)H_DIM * L_DIM * L_DIM) {
        float4 z = {0.f, 0.f, 0.f, 0.f};
        *(float4*)(g_scores + idx) = z;
    }
    int t = blockIdx.x * 256 + threadIdx.x;
    if (t < H_DIM * L_DIM) {
        int h = t / L_DIM, j = t % L_DIM;
        float s = 0.0f;
        for (int e = 0; e < E_DIM; e++) s += mask[((size_t)h * E_DIM + e) * L_DIM + j];
        g_rowmask[t] = s;
    }
}

// ---------------- K3b: row scores (tensor cores, 3xTF32) -------------------------
__global__ __launch_bounds__(256, 2) void row_scores_tc() {
    __shared__ unsigned As_h[16][136], As_l[16][136];
    __shared__ unsigned Bs_h[16][136], Bs_l[16][136];
    const int tid = threadIdx.x;
    const int wid = tid >> 5, lane = tid & 31;
    const int warp_m = (wid >> 1) * 32;
    const int warp_n = (wid & 1) * 64;
    const int r = lane >> 2, c = lane & 3;
    const int it = (blockIdx.x >> 1) * 128;
    const int jt = (blockIdx.x & 1) * 128;
    const int h = blockIdx.y;
    const int e0 = blockIdx.z * 16;

    float acc[2][8][4];
#pragma unroll
    for (int t = 0; t < 2; t++)
#pragma unroll
        for (int u = 0; u < 8; u++)
#pragma unroll
            for (int v = 0; v < 4; v++) acc[t][u][v] = 0.0f;

    for (int e = e0; e < e0 + 16; e++) {
        const float* qbase = g_proj + (size_t)(e * L_DIM) * TD_DIM + h * DH_DIM;
        const float* kbase = qbase + D_DIM;
        for (int k0 = 0; k0 < DH_DIM; k0 += 16) {
#pragma unroll
            for (int q = 0; q < 2; q++) {
                int id = q * 256 + tid;
                int rr = id >> 2;
                int c4 = (id & 3) << 2;
                float4 va = *(const float4*)(qbase + (size_t)(it + rr) * TD_DIM + k0 + c4);
                unsigned hh;
                hh = f2tf32(va.x); As_h[c4 + 0][rr] = hh; As_l[c4 + 0][rr] = f2tf32(va.x - __uint_as_float(hh));
                hh = f2tf32(va.y); As_h[c4 + 1][rr] = hh; As_l[c4 + 1][rr] = f2tf32(va.y - __uint_as_float(hh));
                hh = f2tf32(va.z); As_h[c4 + 2][rr] = hh; As_l[c4 + 2][rr] = f2tf32(va.z - __uint_as_float(hh));
                hh = f2tf32(va.w); As_h[c4 + 3][rr] = hh; As_l[c4 + 3][rr] = f2tf32(va.w - __uint_as_float(hh));
                float4 vb = *(const float4*)(kbase + (size_t)(jt + rr) * TD_DIM + k0 + c4);
                hh = f2tf32(vb.x); Bs_h[c4 + 0][rr] = hh; Bs_l[c4 + 0][rr] = f2tf32(vb.x - __uint_as_float(hh));
                hh = f2tf32(vb.y); Bs_h[c4 + 1][rr] = hh; Bs_l[c4 + 1][rr] = f2tf32(vb.y - __uint_as_float(hh));
                hh = f2tf32(vb.z); Bs_h[c4 + 2][rr] = hh; Bs_l[c4 + 2][rr] = f2tf32(vb.z - __uint_as_float(hh));
                hh = f2tf32(vb.w); Bs_h[c4 + 3][rr] = hh; Bs_l[c4 + 3][rr] = f2tf32(vb.w - __uint_as_float(hh));
            }
            __syncthreads();
#pragma unroll
            for (int k8 = 0; k8 < 16; k8 += 8) {
                unsigned Ah[2][4], Al[2][4];
#pragma unroll
                for (int t = 0; t < 2; t++) {
                    int m = warp_m + t * 16 + r;
                    Ah[t][0] = As_h[k8 + c][m];     Al[t][0] = As_l[k8 + c][m];
                    Ah[t][1] = As_h[k8 + c][m + 8]; Al[t][1] = As_l[k8 + c][m + 8];
                    Ah[t][2] = As_h[k8 + c + 4][m];     Al[t][2] = As_l[k8 + c + 4][m];
                    Ah[t][3] = As_h[k8 + c + 4][m + 8]; Al[t][3] = As_l[k8 + c + 4][m + 8];
                }
#pragma unroll
                for (int u = 0; u < 8; u++) {
                    int n = warp_n + u * 8 + r;
                    unsigned Bh[2], Bl[2];
                    Bh[0] = Bs_h[k8 + c][n];     Bl[0] = Bs_l[k8 + c][n];
                    Bh[1] = Bs_h[k8 + 4 + c][n]; Bl[1] = Bs_l[k8 + 4 + c][n];
#pragma unroll
                    for (int t = 0; t < 2; t++) {
                        mma_tf32(acc[t][u], Ah[t], Bh);
                        mma_tf32(acc[t][u], Ah[t], Bl);
                        mma_tf32(acc[t][u], Al[t], Bh);
                    }
                }
            }
            __syncthreads();
        }
    }

#pragma unroll
    for (int t = 0; t < 2; t++) {
        int row = it + warp_m + t * 16 + r;
#pragma unroll
        for (int u = 0; u < 8; u++) {
            int col = jt + warp_n + u * 8 + c * 2;
            float* p0 = &g_scores[((size_t)h * L_DIM + row) * L_DIM + col];
            atomicAdd(p0, acc[t][u][0]);
            atomicAdd(p0 + 1, acc[t][u][1]);
            float* p1 = &g_scores[((size_t)h * L_DIM + row + 8) * L_DIM + col];
            atomicAdd(p1, acc[t][u][2]);
            atomicAdd(p1 + 1, acc[t][u][3]);
        }
    }
}

// ---------------- K4: softmax over j (adds row mask on the fly) ----------------
__global__ __launch_bounds__(256) void row_softmax_kernel() {
    __shared__ float red[8];
    int h = blockIdx.x / L_DIM;
    float* row = g_scores + (size_t)blockIdx.x * L_DIM;
    float v = row[threadIdx.x] + g_rowmask[h * L_DIM + threadIdx.x];
    float m = block_max256(v, red);
    float p = __expf(v - m);
    float s = block_sum256(p, red);
    row[threadIdx.x] = p / s;
}

// ---------------- K5: row AV + residual (tensor cores, 3xTF32) -------------------
__global__ __launch_bounds__(256) void row_av_tc(const float* __restrict__ x,
                                                 float* __restrict__ out) {
    __shared__ float As[16][136];   // P^T: [j][i]
    __shared__ float Bs[16][68];    // V:   [j][c]
    const int tid = threadIdx.x;
    const int wid = tid >> 5, lane = tid & 31;
    const int warp_m = (wid >> 1) * 32;
    const int warp_n = (wid & 1) * 32;
    const int r = lane >> 2, c = lane & 3;
    const int it = blockIdx.x * 128;
    const int h = blockIdx.y;
    const int e = blockIdx.z;

    const float* pbase = g_scores + (size_t)h * L_DIM * L_DIM;
    const float* vbase = g_proj + (size_t)(e * L_DIM) * TD_DIM + 2 * D_DIM + h * DH_DIM;

    const int rr0 = tid >> 2, rr1 = rr0 + 64;
    const int cc = (tid & 3) << 2;
    const int vj = tid >> 4;
    const int vc = (tid & 15) << 2;

    float acc[2][4][4];
#pragma unroll
    for (int t = 0; t < 2; t++)
#pragma unroll
        for (int u = 0; u < 4; u++)
#pragma unroll
            for (int v = 0; v < 4; v++) acc[t][u][v] = 0.0f;

    for (int kt = 0; kt < 16; kt++) {
        const int j0 = kt * 16;
#pragma unroll
        for (int q = 0; q < 2; q++) {
            int rr = q ? rr1 : rr0;
            float4 p = *(const float4*)(pbase + (size_t)(it + rr) * L_DIM + j0 + cc);
            As[cc + 0][rr] = p.x; As[cc + 1][rr] = p.y;
            As[cc + 2][rr] = p.z; As[cc + 3][rr] = p.w;
        }
        {
            float4 v = *(const float4*)(vbase + (size_t)(j0 + vj) * TD_DIM + vc);
            *(float4*)&Bs[vj][vc] = v;
        }
        __syncthreads();
#pragma unroll
        for (int k8 = 0; k8 < 16; k8 += 8) {
            unsigned Ahi[2][4], Alo[2][4];
#pragma unroll
            for (int t = 0; t < 2; t++) {
                int m = warp_m + t * 16 + r;
                split3(As[k8 + c][m],     Ahi[t][0], Alo[t][0]);
                split3(As[k8 + c][m + 8], Ahi[t][1], Alo[t][1]);
                split3(As[k8 + c + 4][m],     Ahi[t][2], Alo[t][2]);
                split3(As[k8 + c + 4][m + 8], Ahi[t][3], Alo[t][3]);
            }
#pragma unroll
            for (int u = 0; u < 4; u++) {
                int n = warp_n + u * 8 + r;
                unsigned Bh[2], Bl[2];
                split3(Bs[k8 + c][n],     Bh[0], Bl[0]);
                split3(Bs[k8 + 4 + c][n], Bh[1], Bl[1]);
#pragma unroll
                for (int t = 0; t < 2; t++) {
                    mma_tf32(acc[t][u], Ahi[t], Bh);
                    mma_tf32(acc[t][u], Ahi[t], Bl);
                    mma_tf32(acc[t][u], Alo[t], Bh);
                }
            }
        }
        __syncthreads();
    }

#pragma unroll
    for (int t = 0; t < 2; t++) {
        int row = it + warp_m + t * 16 + r;
#pragma unroll
        for (int u = 0; u < 4; u++) {
            int col = warp_n + u * 8 + c * 2;
            size_t off0 = ((size_t)(e * L_DIM + row)) * D_DIM + h * DH_DIM + col;
            size_t off1 = ((size_t)(e * L_DIM + row + 8)) * D_DIM + h * DH_DIM + col;
            float2 x0 = *(const float2*)(x + off0);
            float2 x1 = *(const float2*)(x + off1);
            float2 v0, v1;
            v0.x = x0.x + acc[t][u][0]; v0.y = x0.y + acc[t][u][1];
            v1.x = x1.x + acc[t][u][2]; v1.y = x1.y + acc[t][u][3];
            *(float2*)(out + off0) = v0;
            *(float2*)(out + off1) = v1;
        }
    }
}

// ---------------- K8: fused column attention (tensor cores), one block per (h,l) ----
// Layout (floats): Ks [c=64][136] | Vs [j=128][72] | Ss [j=128][136] (first 64 rows
// alias Qs [c][i]) | red2 [256].  S = QK^T and O = PV via mma tf32 (3-term).
#define CK_STR 136
#define CV_STR 72
#define COL_SMEM_FLOATS (64 * CK_STR + 128 * CV_STR + 128 * CK_STR + 256)
__global__ __launch_bounds__(256) void col_attn_tc(const float* __restrict__ mask,
                                                   float* __restrict__ out) {
    extern __shared__ float sm[];
    float* Ks = sm;                         // [c][j] stride CK_STR
    float* Vs = Ks + 64 * CK_STR;           // [j][c] stride CV_STR
    float* Ss = Vs + 128 * CV_STR;          // [j][i] stride CK_STR
    float* red2 = Ss + 128 * CK_STR;
    float* Qs = Ss;                         // [c][i] alias (first 64 rows)
    const int tid = threadIdx.x;
    const int wid = tid >> 5, lane = tid & 31;
    const int r = lane >> 2, c = lane & 3;
    const int l = blockIdx.x;
    const int h = blockIdx.y;

    const float* qbase = g_proj + (size_t)l * TD_DIM + h * DH_DIM;   // + row*L*TD
    const float* kbase = qbase + D_DIM;
    const float* vbase = qbase + 2 * D_DIM;

    // ---- stage Q [c][i], K [c][j] (transposed, warp-contiguous rows), V [j][c] ----
#pragma unroll
    for (int q = 0; q < 8; q++) {
        int id = q * 256 + tid;                 // 2048 float4 per tensor
        int rr = id & 127;
        int c4 = ((id >> 7) & 15) << 2;
        float4 va = *(const float4*)(qbase + (size_t)rr * L_DIM * TD_DIM + c4);
        Qs[(c4 + 0) * CK_STR + rr] = va.x; Qs[(c4 + 1) * CK_STR + rr] = va.y;
        Qs[(c4 + 2) * CK_STR + rr] = va.z; Qs[(c4 + 3) * CK_STR + rr] = va.w;
        float4 vb = *(const float4*)(kbase + (size_t)rr * L_DIM * TD_DIM + c4);
        Ks[(c4 + 0) * CK_STR + rr] = vb.x; Ks[(c4 + 1) * CK_STR + rr] = vb.y;
        Ks[(c4 + 2) * CK_STR + rr] = vb.z; Ks[(c4 + 3) * CK_STR + rr] = vb.w;
        int rJ = id >> 4;
        int c42 = (id & 15) << 2;
        *(float4*)&Vs[rJ * CV_STR + c42] = *(const float4*)(vbase + (size_t)rJ * L_DIM * TD_DIM + c42);
    }
    __syncthreads();

    // ---- S = Q K^T : M=128 (i), N=128 (j), K=64 (c); warps 4m x 2n ----
    float accS[2][8][4];
    {
        const int warp_m = (wid >> 1) * 32;
        const int warp_n = (wid & 1) * 64;
#pragma unroll
        for (int t = 0; t < 2; t++)
#pragma unroll
            for (int u = 0; u < 8; u++)
#pragma unroll
                for (int v = 0; v < 4; v++) accS[t][u][v] = 0.0f;
#pragma unroll
        for (int k8 = 0; k8 < 64; k8 += 8) {
            unsigned Ahi[2][4], Alo[2][4];
#pragma unroll
            for (int t = 0; t < 2; t++) {
                int m = warp_m + t * 16 + r;
                split3(Qs[(k8 + c) * CK_STR + m],     Ahi[t][0], Alo[t][0]);
                split3(Qs[(k8 + c) * CK_STR + m + 8], Ahi[t][1], Alo[t][1]);
                split3(Qs[(k8 + c + 4) * CK_STR + m],     Ahi[t][2], Alo[t][2]);
                split3(Qs[(k8 + c + 4) * CK_STR + m + 8], Ahi[t][3], Alo[t][3]);
            }
#pragma unroll
            for (int u = 0; u < 8; u++) {
                int n = warp_n + u * 8 + r;
                unsigned Bh[2], Bl[2];
                split3(Ks[(k8 + c) * CK_STR + n],     Bh[0], Bl[0]);
                split3(Ks[(k8 + 4 + c) * CK_STR + n], Bh[1], Bl[1]);
#pragma unroll
                for (int t = 0; t < 2; t++) {
                    mma_tf32(accS[t][u], Ahi[t], Bh);
                    mma_tf32(accS[t][u], Ahi[t], Bl);
                    mma_tf32(accS[t][u], Alo[t], Bh);
                }
            }
        }
    }
    __syncthreads();   // all Qs reads complete before Ss (alias) is written

    // ---- epilogue: S + mask -> Ss[j][i] ----
    {
        const int warp_m = (wid >> 1) * 32;
        const int warp_n = (wid & 1) * 64;
#pragma unroll
        for (int t = 0; t < 2; t++) {
            int m = warp_m + t * 16 + r;
#pragma unroll
            for (int u = 0; u < 8; u++) {
                int j0 = warp_n + u * 8 + c * 2;
                float mk0 = mask[((size_t)h * E_DIM + j0) * L_DIM + l];
                float mk1 = mask[((size_t)h * E_DIM + j0 + 1) * L_DIM + l];
                Ss[j0 * CK_STR + m]           = accS[t][u][0] + mk0;
                Ss[(j0 + 1) * CK_STR + m]     = accS[t][u][1] + mk1;
                Ss[j0 * CK_STR + m + 8]       = accS[t][u][2] + mk0;
                Ss[(j0 + 1) * CK_STR + m + 8] = accS[t][u][3] + mk1;
            }
        }
    }
    __syncthreads();

    // ---- softmax over j for each i: 2 threads per i ----
    {
        const int i = tid & 127;
        const int half = tid >> 7;
        const int j0 = half * 64;
        float m = -3.4e38f;
#pragma unroll 8
        for (int j = 0; j < 64; j++) m = fmaxf(m, Ss[(j0 + j) * CK_STR + i]);
        red2[tid] = m;
        __syncthreads();
        m = fmaxf(red2[i], red2[i + 128]);
        float s = 0.0f;
#pragma unroll 8
        for (int j = 0; j < 64; j++) {
            float p = __expf(Ss[(j0 + j) * CK_STR + i] - m);
            Ss[(j0 + j) * CK_STR + i] = p;
            s += p;
        }
        __syncthreads();
        red2[tid] = s;
        __syncthreads();
        float inv = 1.0f / (red2[i] + red2[i + 128]);
#pragma unroll 8
        for (int j = 0; j < 64; j++) Ss[(j0 + j) * CK_STR + i] *= inv;
    }
    __syncthreads();

    // ---- O = P V : M=128 (i), N=64 (c), K=128 (j); warps 4m x 2n ----
    {
        const int warp_m = (wid >> 1) * 32;
        const int warp_n = (wid & 1) * 32;
        float accO[2][4][4];
#pragma unroll
        for (int t = 0; t < 2; t++)
#pragma unroll
            for (int u = 0; u < 4; u++)
#pragma unroll
                for (int v = 0; v < 4; v++) accO[t][u][v] = 0.0f;
#pragma unroll
        for (int k8 = 0; k8 < 128; k8 += 8) {
            unsigned Ahi[2][4], Alo[2][4];
#pragma unroll
            for (int t = 0; t < 2; t++) {
                int m = warp_m + t * 16 + r;
                split3(Ss[(k8 + c) * CK_STR + m],     Ahi[t][0], Alo[t][0]);
                split3(Ss[(k8 + c) * CK_STR + m + 8], Ahi[t][1], Alo[t][1]);
                split3(Ss[(k8 + c + 4) * CK_STR + m],     Ahi[t][2], Alo[t][2]);
                split3(Ss[(k8 + c + 4) * CK_STR + m + 8], Ahi[t][3], Alo[t][3]);
            }
#pragma unroll
            for (int u = 0; u < 4; u++) {
                int n = warp_n + u * 8 + r;
                unsigned Bh[2], Bl[2];
                split3(Vs[(k8 + c) * CV_STR + n],     Bh[0], Bl[0]);
                split3(Vs[(k8 + 4 + c) * CV_STR + n], Bh[1], Bl[1]);
#pragma unroll
                for (int t = 0; t < 2; t++) {
                    mma_tf32(accO[t][u], Ahi[t], Bh);
                    mma_tf32(accO[t][u], Ahi[t], Bl);
                    mma_tf32(accO[t][u], Alo[t], Bh);
                }
            }
        }

        // epilogue: out[i,l,h,c] += O
#pragma unroll
        for (int t = 0; t < 2; t++) {
            int row = warp_m + t * 16 + r;
#pragma unroll
            for (int u = 0; u < 4; u++) {
                int col = warp_n + u * 8 + c * 2;
                size_t off0 = ((size_t)row * L_DIM + l) * D_DIM + h * DH_DIM + col;
                size_t off1 = ((size_t)(row + 8) * L_DIM + l) * D_DIM + h * DH_DIM + col;
                float2 c0 = *(const float2*)(out + off0);
                float2 c1 = *(const float2*)(out + off1);
                c0.x += accO[t][u][0]; c0.y += accO[t][u][1];
                c1.x += accO[t][u][2]; c1.y += accO[t][u][3];
                *(float2*)(out + off0) = c0;
                *(float2*)(out + off1) = c1;
            }
        }
    }
}

// ---------------- launcher ----------------
extern "C" void kernel_launch(void* const* d_in, const int* in_sizes, int n_in,
                              void* d_out, int out_size) {
    const float* x     = (const float*)d_in[0];
    const float* mask  = (const float*)d_in[1];
    const float* w_row = (const float*)d_in[2];
    const float* b_row = (const float*)d_in[3];
    const float* w_col = (const float*)d_in[4];
    const float* b_col = (const float*)d_in[5];
    const float* g1    = (const float*)d_in[6];
    const float* be1   = (const float*)d_in[7];
    const float* g2    = (const float*)d_in[8];
    const float* be2   = (const float*)d_in[9];
    float* out = (float*)d_out;

    unsigned *wr_hi, *wr_lo, *wc_hi, *wc_lo, *xh, *xl;
    cudaGetSymbolAddress((void**)&wr_hi, g_wr_hi);
    cudaGetSymbolAddress((void**)&wr_lo, g_wr_lo);
    cudaGetSymbolAddress((void**)&wc_hi, g_wc_hi);
    cudaGetSymbolAddress((void**)&wc_lo, g_wc_lo);
    cudaGetSymbolAddress((void**)&xh, g_xh);
    cudaGetSymbolAddress((void**)&xl, g_xl);

    const int col_smem = COL_SMEM_FLOATS * (int)sizeof(float);   // ~142 KB
    cudaFuncSetAttribute(col_attn_tc, cudaFuncAttributeMaxDynamicSharedMemorySize, col_smem);
    cudaFuncSetAttribute(qkv_gemm_tc, cudaFuncAttributeMaxDynamicSharedMemorySize, QKV_SMEM_BYTES);

    const int wsplit_blocks = (TD_DIM * D_DIM) / (256 * 4);   // 1728

    // ---- row attention stage ----
    split_w_kernel<<<wsplit_blocks, 256>>>(w_row, wr_hi, wr_lo);
    split_w_kernel<<<wsplit_blocks, 256>>>(w_col, wc_hi, wc_lo);
    ln_split_kernel<<<N_ROWS, 256>>>(x, g1, be1);
    qkv_gemm_tc<<<dim3(TD_DIM / 128, N_ROWS / 128), 256, QKV_SMEM_BYTES>>>(xh, xl, wr_hi, wr_lo, b_row);
    scores_zero_kernel<<<(H_DIM * L_DIM * L_DIM) / 1024, 256>>>(mask);
    row_scores_tc<<<dim3(4, H_DIM, 8), 256>>>();
    row_softmax_kernel<<<H_DIM * L_DIM, 256>>>();
    row_av_tc<<<dim3(2, H_DIM, E_DIM), 256>>>(x, out);   // out = x + row_out

    // ---- column attention stage ----
    ln_split_kernel<<<N_ROWS, 256>>>(out, g2, be2);
    qkv_gemm_tc<<<dim3(TD_DIM / 128, N_ROWS / 128), 256, QKV_SMEM_BYTES>>>(xh, xl, wc_hi, wc_lo, b_col);
    col_attn_tc<<<dim3(L_DIM, H_DIM), 256, col_smem>>>(mask, out);  // out += col_out
}